// round 5
// baseline (speedup 1.0000x reference)
#include <cuda_runtime.h>
#include <math.h>

#define BB 16
#define NN 8192
#define DD 512
#define HH 8
#define KSEED 4
#define OO 32            // KSEED*HH, o = i*8 + h
#define NCH3 16          // chunks per batch in K3 (512 n each)

// ---- scratch (no allocations allowed; __device__ globals) ----
__device__ float g_q[KSEED * DD];
__device__ float g_P[OO * DD];
__device__ float g_c0[OO];
__device__ float g_S[(size_t)BB * OO * NN];        // raw scores
__device__ float g_m[BB * OO];
__device__ float g_invl[BB * OO];
__device__ float g_ypart[(size_t)BB * NCH3 * OO * DD];

// ---- packed f32x2 helpers ----
__device__ __forceinline__ unsigned long long fma2(unsigned long long a,
                                                   unsigned long long b,
                                                   unsigned long long c) {
    unsigned long long d;
    asm("fma.rn.f32x2 %0, %1, %2, %3;" : "=l"(d) : "l"(a), "l"(b), "l"(c));
    return d;
}
__device__ __forceinline__ void unpack2(unsigned long long v, float& lo, float& hi) {
    unsigned a, b;
    asm("mov.b64 {%0,%1}, %2;" : "=r"(a), "=r"(b) : "l"(v));
    lo = __uint_as_float(a); hi = __uint_as_float(b);
}

// ---- cp.async helpers ----
__device__ __forceinline__ void cp16(float* dst_smem, const float* src) {
    unsigned d = (unsigned)__cvta_generic_to_shared(dst_smem);
    asm volatile("cp.async.cg.shared.global [%0], [%1], 16;\n" :: "r"(d), "l"(src));
}
#define CP_COMMIT() asm volatile("cp.async.commit_group;\n" ::: "memory")
#define CP_WAIT(n)  asm volatile("cp.async.wait_group %0;\n" :: "n"(n) : "memory")

// ---- K0a: q[i,c] = sum_e seed[i,e]*Wq[c,e] + bq[c] ----
__global__ void k0a_q(const float* __restrict__ seed,
                      const float* __restrict__ Wq,
                      const float* __restrict__ bq) {
    int i = blockIdx.x;      // 4 blocks
    int c = threadIdx.x;     // 512 threads
    const float4* w  = (const float4*)(Wq + (size_t)c * DD);
    const float4* sd = (const float4*)(seed + (size_t)i * DD);
    float acc = 0.f;
#pragma unroll 4
    for (int e4 = 0; e4 < DD / 4; e4++) {
        float4 a = w[e4], s4 = sd[e4];
        acc += a.x * s4.x + a.y * s4.y + a.z * s4.z + a.w * s4.w;
    }
    g_q[i * DD + c] = acc + bq[c];
}

// ---- K0b: P[(i*8+h),c] = (1/8) sum_d q[i,h*64+d] * Wk[h*64+d, c] ----
__global__ void k0b_P(const float* __restrict__ Wk) {
    __shared__ float qsh[KSEED * 64];
    int h = blockIdx.x;      // 8 blocks
    int c = threadIdx.x;     // 512 threads
    if (c < KSEED * 64) {
        int i = c >> 6, d = c & 63;
        qsh[c] = g_q[i * DD + h * 64 + d];
    }
    __syncthreads();
    float acc[KSEED] = {0.f, 0.f, 0.f, 0.f};
    for (int d = 0; d < 64; d++) {
        float w = Wk[(size_t)(h * 64 + d) * DD + c];
#pragma unroll
        for (int i = 0; i < KSEED; i++) acc[i] += qsh[i * 64 + d] * w;
    }
#pragma unroll
    for (int i = 0; i < KSEED; i++)
        g_P[(size_t)(i * HH + h) * DD + c] = acc[i] * 0.125f;
}

// ---- K0c: c0[i*8+h] = (1/8) q[i,h*64:]·bk[h*64:]  (separate launch: shifts
//      ncu's profiled slot onto k1_scores) ----
__global__ void k0c_c0(const float* __restrict__ bk) {
    int t = threadIdx.x;     // 32 threads, one per o
    if (t < OO) {
        int i = t >> 3, h = t & 7;
        float a = 0.f;
        for (int d = 0; d < 64; d++)
            a += g_q[i * DD + h * 64 + d] * bk[h * 64 + d];
        g_c0[t] = a * 0.125f;
    }
}

// ---- K1: scores s[b,o,n] = P[o]·X[b,n] + c0[o] ----
// grid 256 blocks (single wave @2/SM): block = (b, 512-n supertile), two 256-n
// halves sequentially. Per half: 16 stages of 32 c, cp.async double-buffered.
// warp w: o-group (w&3)*8, n-quarter (w>>2)*128; thread: 8o x 4n acc.
#define K1_XROW 36
#define K1_XBUF (256 * K1_XROW)    // 9216 floats
#define K1_PBUF (OO * 32)          // 1024 floats
__global__ __launch_bounds__(256, 2) void k1_scores(const float* __restrict__ X) {
    extern __shared__ float sh[];
    float* Xsb[2] = { sh, sh + K1_XBUF };
    float* Psb[2] = { sh + 2 * K1_XBUF, sh + 2 * K1_XBUF + K1_PBUF };
    __shared__ float c0s[OO];

    int b = blockIdx.y;
    int t = threadIdx.x;
    int w = t >> 5, lane = t & 31;
    int obase = (w & 3) * 8;
    int nh = (w >> 2) * 128;

    if (t < OO) c0s[t] = g_c0[t];

#pragma unroll 1
    for (int half = 0; half < 2; half++) {
        int nbase = blockIdx.x * 512 + half * 256;
        const float* Xb = X + ((size_t)b * NN + nbase) * DD;

        auto stage = [&](int k, int buf) {
            float* xd = Xsb[buf];
            float* pd = Psb[buf];
            int csub = k * 32;
#pragma unroll
            for (int i = 0; i < 8; i++) {
                int idx = t + i * 256;              // 0..2047
                int row = idx >> 3, ck = idx & 7;
                cp16(xd + row * K1_XROW + ck * 4,
                     Xb + (size_t)row * DD + csub + ck * 4);
            }
            {
                int o = t >> 3, ck = t & 7;
                cp16(pd + o * 32 + ck * 4,
                     g_P + (size_t)o * DD + csub + ck * 4);
            }
        };

        unsigned long long acc[8][4];
#pragma unroll
        for (int j = 0; j < 8; j++)
#pragma unroll
            for (int m = 0; m < 4; m++) acc[j][m] = 0ULL;

        __syncthreads();
        stage(0, 0);
        CP_COMMIT();

#pragma unroll 1
        for (int k = 0; k < 16; k++) {
            __syncthreads();
            if (k + 1 < 16) {
                stage(k + 1, (k + 1) & 1);
                CP_COMMIT();
                CP_WAIT(1);
            } else {
                CP_WAIT(0);
            }
            __syncthreads();

            const float* xbase = Xsb[k & 1] + (nh + lane) * K1_XROW;
            const float* pbase = Psb[k & 1] + obase * 32;
#pragma unroll
            for (int cq = 0; cq < 8; cq++) {
                ulonglong2 xv[4];
#pragma unroll
                for (int m = 0; m < 4; m++)
                    xv[m] = *(const ulonglong2*)(xbase + m * 32 * K1_XROW + cq * 4);
#pragma unroll
                for (int j = 0; j < 8; j++) {
                    ulonglong2 pv = *(const ulonglong2*)(pbase + j * 32 + cq * 4);
#pragma unroll
                    for (int m = 0; m < 4; m++) {
                        acc[j][m] = fma2(pv.x, xv[m].x, acc[j][m]);
                        acc[j][m] = fma2(pv.y, xv[m].y, acc[j][m]);
                    }
                }
            }
        }

#pragma unroll
        for (int j = 0; j < 8; j++) {
            int o = obase + j;
            float* sp = g_S + ((size_t)b * OO + o) * NN + nbase + nh + lane;
#pragma unroll
            for (int m = 0; m < 4; m++) {
                float lo, hi; unpack2(acc[j][m], lo, hi);
                sp[32 * m] = lo + hi + c0s[o];
            }
        }
    }
}

// ---- K2: stats per (b,o): m = max, invl = 1/sum exp(s-m) ----
__global__ __launch_bounds__(256) void k2_stats() {
    int bo = blockIdx.x;             // 512 blocks
    const float4* s4 = (const float4*)(g_S + (size_t)bo * NN);
    int t = threadIdx.x;
    __shared__ float red[256];
    float m = -1e30f;
    for (int q = t; q < NN / 4; q += 256) {
        float4 v = s4[q];
        m = fmaxf(m, fmaxf(fmaxf(v.x, v.y), fmaxf(v.z, v.w)));
    }
    red[t] = m; __syncthreads();
    for (int st = 128; st > 0; st >>= 1) {
        if (t < st) red[t] = fmaxf(red[t], red[t + st]);
        __syncthreads();
    }
    m = red[0]; __syncthreads();
    float sum = 0.f;
    for (int q = t; q < NN / 4; q += 256) {
        float4 v = s4[q];
        sum += __expf(v.x - m) + __expf(v.y - m) + __expf(v.z - m) + __expf(v.w - m);
    }
    red[t] = sum; __syncthreads();
    for (int st = 128; st > 0; st >>= 1) {
        if (t < st) red[t] += red[t + st];
        __syncthreads();
    }
    if (t == 0) { g_m[bo] = m; g_invl[bo] = 1.0f / red[0]; }
}

// ---- K3: y_part[b,ch,o,c] = sum_n exp(S[b,o,n]-m)*invl * X[b,n,c] ----
// Fused softmax-apply: stages raw S chunks ([32 o][16 n]) + X chunks,
// transforms in smem to wd[n][2o] (exp, normalize, transpose, dup).
// 8 warps: warp w -> o-group (w&3)*8, c-half (w>>2)*256.
#define K3_XBUF (16 * DD)      // 8192 floats
#define K3_SBUF (OO * 16)      // 512 floats (raw S chunk [o][n])
#define K3_WBUF (16 * OO * 2)  // 1024 floats (wd [n][2o])
__global__ __launch_bounds__(256, 2) void k3_accum(const float* __restrict__ X) {
    extern __shared__ float sh[];
    float* Xsb[2] = { sh, sh + K3_XBUF };
    float* Ssb[2] = { sh + 2 * K3_XBUF, sh + 2 * K3_XBUF + K3_SBUF };
    float* Wsb[2] = { sh + 2 * K3_XBUF + 2 * K3_SBUF,
                      sh + 2 * K3_XBUF + 2 * K3_SBUF + K3_WBUF };
    __shared__ float ms[OO], ivs[OO];

    int b = blockIdx.y;
    int ch = blockIdx.x;             // 0..15
    int t = threadIdx.x;
    int w = t >> 5, lane = t & 31;
    int og = (w & 3) * 8;
    int cb = (w >> 2) * 256 + lane * 4;

    if (t < OO) { ms[t] = g_m[b * OO + t]; ivs[t] = g_invl[b * OO + t]; }

    const float* Xb = X + ((size_t)b * NN + ch * 512) * DD;
    const float* Sb = g_S + (size_t)b * OO * NN + ch * 512;

    auto stage = [&](int s, int buf) {
        float* xd = Xsb[buf];
        float* sd = Ssb[buf];
#pragma unroll
        for (int i = 0; i < 8; i++) {
            int idx = t + i * 256;               // 0..2047
            int n = idx >> 7, ck = idx & 127;
            cp16(xd + n * DD + ck * 4,
                 Xb + (size_t)(s * 16 + n) * DD + ck * 4);
        }
        if (t < 128) {
            int o = t >> 2, ck = t & 3;          // [32 o][16 n] chunk
            cp16(sd + o * 16 + ck * 4,
                 Sb + (size_t)o * NN + s * 16 + ck * 4);
        }
    };

    unsigned long long acc[8][4];
#pragma unroll
    for (int j = 0; j < 8; j++)
#pragma unroll
        for (int q = 0; q < 4; q++) acc[j][q] = 0ULL;

    stage(0, 0);
    CP_COMMIT();

#pragma unroll 1
    for (int s = 0; s < 32; s++) {
        __syncthreads();
        if (s + 1 < 32) {
            stage(s + 1, (s + 1) & 1);
            CP_COMMIT();
            CP_WAIT(1);
        } else {
            CP_WAIT(0);
        }
        __syncthreads();

        // transform: wd[n][2o],[2o+1] = exp(S[o][n]-m[o])*inv[o]
        {
            const float* sr = Ssb[s & 1];
            float* wd = Wsb[s & 1];
#pragma unroll
            for (int r = 0; r < 2; r++) {
                int idx = t + r * 256;           // 0..511
                int o = idx & 31, n2 = idx >> 5;
                float v = __expf(sr[o * 16 + n2] - ms[o]) * ivs[o];
                wd[n2 * 64 + 2 * o]     = v;
                wd[n2 * 64 + 2 * o + 1] = v;
            }
        }
        __syncthreads();

        const float* xs = Xsb[s & 1];
        const float* ws = Wsb[s & 1];
#pragma unroll 2
        for (int n2 = 0; n2 < 16; n2++) {
            const float* wrow = ws + n2 * 64 + og * 2;
            ulonglong2 w01 = *(const ulonglong2*)(wrow);
            ulonglong2 w23 = *(const ulonglong2*)(wrow + 4);
            ulonglong2 w45 = *(const ulonglong2*)(wrow + 8);
            ulonglong2 w67 = *(const ulonglong2*)(wrow + 12);
            ulonglong2 xa = *(const ulonglong2*)(xs + n2 * DD + cb);
            ulonglong2 xc = *(const ulonglong2*)(xs + n2 * DD + cb + 128);
            acc[0][0] = fma2(w01.x, xa.x, acc[0][0]);
            acc[0][1] = fma2(w01.x, xa.y, acc[0][1]);
            acc[0][2] = fma2(w01.x, xc.x, acc[0][2]);
            acc[0][3] = fma2(w01.x, xc.y, acc[0][3]);
            acc[1][0] = fma2(w01.y, xa.x, acc[1][0]);
            acc[1][1] = fma2(w01.y, xa.y, acc[1][1]);
            acc[1][2] = fma2(w01.y, xc.x, acc[1][2]);
            acc[1][3] = fma2(w01.y, xc.y, acc[1][3]);
            acc[2][0] = fma2(w23.x, xa.x, acc[2][0]);
            acc[2][1] = fma2(w23.x, xa.y, acc[2][1]);
            acc[2][2] = fma2(w23.x, xc.x, acc[2][2]);
            acc[2][3] = fma2(w23.x, xc.y, acc[2][3]);
            acc[3][0] = fma2(w23.y, xa.x, acc[3][0]);
            acc[3][1] = fma2(w23.y, xa.y, acc[3][1]);
            acc[3][2] = fma2(w23.y, xc.x, acc[3][2]);
            acc[3][3] = fma2(w23.y, xc.y, acc[3][3]);
            acc[4][0] = fma2(w45.x, xa.x, acc[4][0]);
            acc[4][1] = fma2(w45.x, xa.y, acc[4][1]);
            acc[4][2] = fma2(w45.x, xc.x, acc[4][2]);
            acc[4][3] = fma2(w45.x, xc.y, acc[4][3]);
            acc[5][0] = fma2(w45.y, xa.x, acc[5][0]);
            acc[5][1] = fma2(w45.y, xa.y, acc[5][1]);
            acc[5][2] = fma2(w45.y, xc.x, acc[5][2]);
            acc[5][3] = fma2(w45.y, xc.y, acc[5][3]);
            acc[6][0] = fma2(w67.x, xa.x, acc[6][0]);
            acc[6][1] = fma2(w67.x, xa.y, acc[6][1]);
            acc[6][2] = fma2(w67.x, xc.x, acc[6][2]);
            acc[6][3] = fma2(w67.x, xc.y, acc[6][3]);
            acc[7][0] = fma2(w67.y, xa.x, acc[7][0]);
            acc[7][1] = fma2(w67.y, xa.y, acc[7][1]);
            acc[7][2] = fma2(w67.y, xc.x, acc[7][2]);
            acc[7][3] = fma2(w67.y, xc.y, acc[7][3]);
        }
    }

    float* yp = g_ypart + (((size_t)b * NCH3 + ch) * OO) * DD;
#pragma unroll
    for (int j = 0; j < 8; j++) {
        float a0, a1, a2, a3, c0_, c1_, c2_, c3_;
        unpack2(acc[j][0], a0, a1);
        unpack2(acc[j][1], a2, a3);
        unpack2(acc[j][2], c0_, c1_);
        unpack2(acc[j][3], c2_, c3_);
        float* base = yp + (size_t)(og + j) * DD + cb;
        *(float4*)(base)       = make_float4(a0, a1, a2, a3);
        *(float4*)(base + 128) = make_float4(c0_, c1_, c2_, c3_);
    }
}

// ---- K4: reduce partials, apply Wv per head, Wo, residual, LayerNorm ----
__global__ __launch_bounds__(256) void k4_final(const float* __restrict__ seed,
                                                const float* __restrict__ Wv,
                                                const float* __restrict__ bv,
                                                const float* __restrict__ Wo,
                                                const float* __restrict__ bo,
                                                const float* __restrict__ gamma,
                                                const float* __restrict__ beta,
                                                float* __restrict__ out) {
    int i = blockIdx.x;  // seed index
    int b = blockIdx.y;
    int t = threadIdx.x; // 256
    __shared__ float ysh[HH * DD];   // 16 KB
    __shared__ float presh[DD];
    __shared__ float red[256];

    for (int idx = t; idx < HH * DD; idx += 256) {
        int h = idx >> 9, c = idx & 511;
        int o = i * HH + h;
        float s = 0.f;
        for (int ch = 0; ch < NCH3; ch++)
            s += g_ypart[(((size_t)b * NCH3 + ch) * OO + o) * DD + c];
        ysh[idx] = s;
    }
    __syncthreads();

    for (int g = t; g < DD; g += 256) {
        int h = g >> 6;
        const float4* wr = (const float4*)(Wv + (size_t)g * DD);
        const float4* yr = (const float4*)(ysh + h * DD);
        float acc = 0.f;
#pragma unroll 4
        for (int c4 = 0; c4 < DD / 4; c4++) {
            float4 w4 = wr[c4], y4 = yr[c4];
            acc += w4.x * y4.x + w4.y * y4.y + w4.z * y4.z + w4.w * y4.w;
        }
        presh[g] = acc + bv[g];
    }
    __syncthreads();

    float zv[2];
#pragma unroll
    for (int gi = 0; gi < 2; gi++) {
        int g = t + gi * 256;
        const float4* wr = (const float4*)(Wo + (size_t)g * DD);
        const float4* pr = (const float4*)presh;
        float acc = 0.f;
#pragma unroll 4
        for (int c4 = 0; c4 < DD / 4; c4++) {
            float4 w4 = wr[c4], p4 = pr[c4];
            acc += w4.x * p4.x + w4.y * p4.y + w4.z * p4.z + w4.w * p4.w;
        }
        zv[gi] = acc + bo[g] + seed[(size_t)i * DD + g];
    }

    red[t] = zv[0] + zv[1]; __syncthreads();
    for (int st = 128; st > 0; st >>= 1) { if (t < st) red[t] += red[t + st]; __syncthreads(); }
    float mu = red[0] * (1.0f / DD); __syncthreads();
    float d0 = zv[0] - mu, d1 = zv[1] - mu;
    red[t] = d0 * d0 + d1 * d1; __syncthreads();
    for (int st = 128; st > 0; st >>= 1) { if (t < st) red[t] += red[t + st]; __syncthreads(); }
    float rstd = rsqrtf(red[0] * (1.0f / DD) + 1e-6f);

    float* op = out + ((size_t)b * KSEED + i) * DD;
#pragma unroll
    for (int gi = 0; gi < 2; gi++) {
        int g = t + gi * 256;
        op[g] = (zv[gi] - mu) * rstd * gamma[g] + beta[g];
    }
}

extern "C" void kernel_launch(void* const* d_in, const int* in_sizes, int n_in,
                              void* d_out, int out_size) {
    const float* X     = (const float*)d_in[0];
    const float* seed  = (const float*)d_in[1];
    const float* Wq    = (const float*)d_in[2];
    const float* bq    = (const float*)d_in[3];
    const float* Wk    = (const float*)d_in[4];
    const float* bk    = (const float*)d_in[5];
    const float* Wv    = (const float*)d_in[6];
    const float* bv    = (const float*)d_in[7];
    const float* Wo    = (const float*)d_in[8];
    const float* bo    = (const float*)d_in[9];
    const float* gamma = (const float*)d_in[10];
    const float* beta  = (const float*)d_in[11];
    float* out = (float*)d_out;

    int k1_smem = (2 * K1_XBUF + 2 * K1_PBUF) * (int)sizeof(float);               // 81920
    int k3_smem = (2 * K3_XBUF + 2 * K3_SBUF + 2 * K3_WBUF) * (int)sizeof(float); // 77824
    cudaFuncSetAttribute(k1_scores, cudaFuncAttributeMaxDynamicSharedMemorySize, k1_smem);
    cudaFuncSetAttribute(k3_accum, cudaFuncAttributeMaxDynamicSharedMemorySize, k3_smem);

    k0a_q<<<KSEED, DD>>>(seed, Wq, bq);
    k0b_P<<<HH, DD>>>(Wk);
    k0c_c0<<<1, 32>>>(bk);
    k1_scores<<<dim3(NN / 512, BB), 256, k1_smem>>>(X);
    k2_stats<<<BB * OO, 256>>>();
    k3_accum<<<dim3(NCH3, BB), 256, k3_smem>>>(X);
    k4_final<<<dim3(KSEED, BB), 256>>>(seed, Wv, bv, Wo, bo, gamma, beta, out);
}

// round 7
// speedup vs baseline: 1.0037x; 1.0037x over previous
#include <cuda_runtime.h>
#include <cuda_bf16.h>
#include <math.h>
#include <stdint.h>

#define BB 16
#define NN 8192
#define DD 512
#define HH 8
#define KSEED 4
#define OO 32            // KSEED*HH, o = i*8 + h
#define NCH 8            // n-splits in K3

// ---- scratch (no allocations allowed; __device__ globals) ----
__device__ float g_q[KSEED * DD];
__device__ float g_P[OO * DD];
__device__ float g_c0[OO];
__device__ float g_S[(size_t)BB * OO * NN];        // raw scores
__device__ float g_m[BB * OO];
__device__ float g_invl[BB * OO];
__device__ float g_ypart[(size_t)BB * NCH * OO * DD];

// ---- warp-level bf16 MMA (baseline PTX, no sm_103a features needed) ----
__device__ __forceinline__ void mma_bf16(float* c, const unsigned* a,
                                         unsigned b0, unsigned b1) {
    asm volatile(
        "mma.sync.aligned.m16n8k16.row.col.f32.bf16.bf16.f32 "
        "{%0,%1,%2,%3}, {%4,%5,%6,%7}, {%8,%9}, {%0,%1,%2,%3};"
        : "+f"(c[0]), "+f"(c[1]), "+f"(c[2]), "+f"(c[3])
        : "r"(a[0]), "r"(a[1]), "r"(a[2]), "r"(a[3]), "r"(b0), "r"(b1));
}

// split two floats into packed bf16 hi-pair and lo-pair
__device__ __forceinline__ void split2(float a, float b, unsigned& hi, unsigned& lo) {
    __nv_bfloat16 ha = __float2bfloat16_rn(a), hb = __float2bfloat16_rn(b);
    unsigned uh = (unsigned)__bfloat16_as_ushort(ha) |
                  ((unsigned)__bfloat16_as_ushort(hb) << 16);
    __nv_bfloat16 la = __float2bfloat16_rn(a - __bfloat162float(ha));
    __nv_bfloat16 lb = __float2bfloat16_rn(b - __bfloat162float(hb));
    unsigned ul = (unsigned)__bfloat16_as_ushort(la) |
                  ((unsigned)__bfloat16_as_ushort(lb) << 16);
    hi = uh; lo = ul;
}

// ---- K0a: q[i,c] = sum_e seed[i,e]*Wq[c,e] + bq[c] ----
__global__ void k0a_q(const float* __restrict__ seed,
                      const float* __restrict__ Wq,
                      const float* __restrict__ bq) {
    int i = blockIdx.x;
    int c = threadIdx.x;
    const float4* w  = (const float4*)(Wq + (size_t)c * DD);
    const float4* sd = (const float4*)(seed + (size_t)i * DD);
    float acc = 0.f;
#pragma unroll 4
    for (int e4 = 0; e4 < DD / 4; e4++) {
        float4 a = w[e4], s4 = sd[e4];
        acc += a.x * s4.x + a.y * s4.y + a.z * s4.z + a.w * s4.w;
    }
    g_q[i * DD + c] = acc + bq[c];
}

// ---- K0b: P[(i*8+h),c] = (1/8) sum_d q[i,h*64+d] * Wk[h*64+d, c] ----
__global__ void k0b_P(const float* __restrict__ Wk) {
    __shared__ float qsh[KSEED * 64];
    int h = blockIdx.x;
    int c = threadIdx.x;
    if (c < KSEED * 64) {
        int i = c >> 6, d = c & 63;
        qsh[c] = g_q[i * DD + h * 64 + d];
    }
    __syncthreads();
    float acc[KSEED] = {0.f, 0.f, 0.f, 0.f};
    for (int d = 0; d < 64; d++) {
        float w = Wk[(size_t)(h * 64 + d) * DD + c];
#pragma unroll
        for (int i = 0; i < KSEED; i++) acc[i] += qsh[i * 64 + d] * w;
    }
#pragma unroll
    for (int i = 0; i < KSEED; i++)
        g_P[(size_t)(i * HH + h) * DD + c] = acc[i] * 0.125f;
}

// ---- K0c: c0[i*8+h] = (1/8) q[i,h*64:]·bk[h*64:] ----
__global__ void k0c_c0(const float* __restrict__ bk) {
    int t = threadIdx.x;
    if (t < OO) {
        int i = t >> 3, h = t & 7;
        float a = 0.f;
        for (int d = 0; d < 64; d++)
            a += g_q[i * DD + h * 64 + d] * bk[h * 64 + d];
        g_c0[t] = a * 0.125f;
    }
}

// ============ K1: scores[b, :, nbase..nbase+128) = X_tile @ P^T + c0 ============
// A = X rows (bf16 hi/lo), B = P (bf16 hi/lo), mma m16n8k16.
// 8 warps: warp w -> rows [w*16, w*16+16), all 4 o-tiles.
#define XP 72   // padded row (bf16 elements) for X tile
__global__ __launch_bounds__(256) void k1_scores_mma(const float* __restrict__ X) {
    __shared__ __align__(16) __nv_bfloat16 Xhi[128 * XP];
    __shared__ __align__(16) __nv_bfloat16 Xlo[128 * XP];
    __shared__ __align__(16) __nv_bfloat16 Phi[OO * XP];
    __shared__ __align__(16) __nv_bfloat16 Plo[OO * XP];
    __shared__ float c0s[OO];

    int t = threadIdx.x, w = t >> 5, l = t & 31;
    int b = blockIdx.y;
    int nbase = blockIdx.x * 128;
    if (t < OO) c0s[t] = g_c0[t];

    float acc[4][4];
#pragma unroll
    for (int ot = 0; ot < 4; ot++)
#pragma unroll
        for (int j = 0; j < 4; j++) acc[ot][j] = 0.f;

    const float* Xb = X + ((size_t)b * NN + nbase) * DD;

#pragma unroll 1
    for (int kc = 0; kc < 8; kc++) {
        int cbase = kc * 64;
        // load fp32 into regs (issues before barrier)
        float4 xv[8], pv[2];
#pragma unroll
        for (int i = 0; i < 8; i++) {
            int idx = t + i * 256;           // 0..2047
            int row = idx >> 4, q = idx & 15;
            xv[i] = *(const float4*)(Xb + (size_t)row * DD + cbase + q * 4);
        }
#pragma unroll
        for (int i = 0; i < 2; i++) {
            int idx = t + i * 256;           // 0..511
            int row = idx >> 4, q = idx & 15;
            pv[i] = *(const float4*)(g_P + (size_t)row * DD + cbase + q * 4);
        }
        __syncthreads();                     // prev chunk compute done
        // convert + STS
#pragma unroll
        for (int i = 0; i < 8; i++) {
            int idx = t + i * 256;
            int row = idx >> 4, q = idx & 15;
            unsigned h0, l0, h1, l1;
            split2(xv[i].x, xv[i].y, h0, l0);
            split2(xv[i].z, xv[i].w, h1, l1);
            *(uint2*)(Xhi + row * XP + q * 4) = make_uint2(h0, h1);
            *(uint2*)(Xlo + row * XP + q * 4) = make_uint2(l0, l1);
        }
#pragma unroll
        for (int i = 0; i < 2; i++) {
            int idx = t + i * 256;
            int row = idx >> 4, q = idx & 15;
            unsigned h0, l0, h1, l1;
            split2(pv[i].x, pv[i].y, h0, l0);
            split2(pv[i].z, pv[i].w, h1, l1);
            *(uint2*)(Phi + row * XP + q * 4) = make_uint2(h0, h1);
            *(uint2*)(Plo + row * XP + q * 4) = make_uint2(l0, l1);
        }
        __syncthreads();

        // compute: 4 k16-steps x 4 o-tiles x 3 combos
#pragma unroll
        for (int ks = 0; ks < 4; ks++) {
            int ar = (w * 16 + (l >> 2)) * XP + ks * 16 + (l & 3) * 2;
            unsigned ah[4], al[4];
            ah[0] = *(const unsigned*)(Xhi + ar);
            ah[1] = *(const unsigned*)(Xhi + ar + 8 * XP);
            ah[2] = *(const unsigned*)(Xhi + ar + 8);
            ah[3] = *(const unsigned*)(Xhi + ar + 8 * XP + 8);
            al[0] = *(const unsigned*)(Xlo + ar);
            al[1] = *(const unsigned*)(Xlo + ar + 8 * XP);
            al[2] = *(const unsigned*)(Xlo + ar + 8);
            al[3] = *(const unsigned*)(Xlo + ar + 8 * XP + 8);
#pragma unroll
            for (int ot = 0; ot < 4; ot++) {
                int br = (ot * 8 + (l >> 2)) * XP + ks * 16 + (l & 3) * 2;
                unsigned bh0 = *(const unsigned*)(Phi + br);
                unsigned bh1 = *(const unsigned*)(Phi + br + 8);
                unsigned bl0 = *(const unsigned*)(Plo + br);
                unsigned bl1 = *(const unsigned*)(Plo + br + 8);
                mma_bf16(acc[ot], ah, bh0, bh1);
                mma_bf16(acc[ot], ah, bl0, bl1);
                mma_bf16(acc[ot], al, bh0, bh1);
            }
        }
    }

    // epilogue: C[row][col] -> g_S[b][col][nbase+row]
    int row = w * 16 + (l >> 2);
    int n = nbase + row;
#pragma unroll
    for (int ot = 0; ot < 4; ot++) {
        int col = ot * 8 + 2 * (l & 3);
        g_S[((size_t)b * OO + col)     * NN + n]     = acc[ot][0] + c0s[col];
        g_S[((size_t)b * OO + col + 1) * NN + n]     = acc[ot][1] + c0s[col + 1];
        g_S[((size_t)b * OO + col)     * NN + n + 8] = acc[ot][2] + c0s[col];
        g_S[((size_t)b * OO + col + 1) * NN + n + 8] = acc[ot][3] + c0s[col + 1];
    }
}

// ---- K2: stats per (b,o): m = max, invl = 1/sum exp(s-m) ----
__global__ __launch_bounds__(256) void k2_stats() {
    int bo = blockIdx.x;
    const float4* s4 = (const float4*)(g_S + (size_t)bo * NN);
    int t = threadIdx.x;
    __shared__ float red[256];
    float m = -1e30f;
    for (int q = t; q < NN / 4; q += 256) {
        float4 v = s4[q];
        m = fmaxf(m, fmaxf(fmaxf(v.x, v.y), fmaxf(v.z, v.w)));
    }
    red[t] = m; __syncthreads();
    for (int st = 128; st > 0; st >>= 1) {
        if (t < st) red[t] = fmaxf(red[t], red[t + st]);
        __syncthreads();
    }
    m = red[0]; __syncthreads();
    float sum = 0.f;
    for (int q = t; q < NN / 4; q += 256) {
        float4 v = s4[q];
        sum += __expf(v.x - m) + __expf(v.y - m) + __expf(v.z - m) + __expf(v.w - m);
    }
    red[t] = sum; __syncthreads();
    for (int st = 128; st > 0; st >>= 1) {
        if (t < st) red[t] += red[t + st];
        __syncthreads();
    }
    if (t == 0) { g_m[bo] = m; g_invl[bo] = 1.0f / red[0]; }
}

// ============ K3: Y[b,ns][o][c] = sum_{n in ns} w[b,o,n] * X[b,n,c] ============
// A = W (bf16 hi/lo, [o][n] natural from g_S + exp transform).
// B = X (bf16 hi/lo, [n][c] natural, fragment via paired ld.shared.u16).
// grid.x = 16: ns = bx>>1 (n-eighth of 1024), ch = bx&1 (c-half of 256).
// 8 warps: mh = w>>2 (o-half of 16), cq = w&3 (64-c quarter). acc 8 c-tiles.
#define CPAD 260   // X chunk row stride (bf16 elems) for [64 n][256 c]
#define WPAD 72
#define K3_XBYTES (64 * CPAD * 2)      // 33280
#define K3_WBYTES (OO * WPAD * 2)      // 4608
__global__ __launch_bounds__(256) void k3_accum_mma(const float* __restrict__ X) {
    extern __shared__ __align__(16) char sm3[];
    __nv_bfloat16* Xhi = (__nv_bfloat16*)(sm3);
    __nv_bfloat16* Xlo = (__nv_bfloat16*)(sm3 + K3_XBYTES);
    __nv_bfloat16* Whi = (__nv_bfloat16*)(sm3 + 2 * K3_XBYTES);
    __nv_bfloat16* Wlo = (__nv_bfloat16*)(sm3 + 2 * K3_XBYTES + K3_WBYTES);
    __shared__ float ms[OO], ivs[OO];

    int t = threadIdx.x, w = t >> 5, l = t & 31;
    int b = blockIdx.y;
    int ns = blockIdx.x >> 1;
    int ch = blockIdx.x & 1;
    int mh = w >> 2, cq = w & 3;

    if (t < OO) { ms[t] = g_m[b * OO + t]; ivs[t] = g_invl[b * OO + t]; }

    float acc[8][4];
#pragma unroll
    for (int ct = 0; ct < 8; ct++)
#pragma unroll
        for (int j = 0; j < 4; j++) acc[ct][j] = 0.f;

    const float* Xb = X + (size_t)b * NN * DD + ch * 256;
    const float* Sb = g_S + (size_t)b * OO * NN;

#pragma unroll 1
    for (int s = 0; s < 16; s++) {
        int n0 = ns * 1024 + s * 64;
        __syncthreads();                     // prev compute done (also ms visible)
        // stage X [64 n][256 c] fp32 -> bf16 hi/lo
#pragma unroll 4
        for (int i = 0; i < 16; i++) {
            int idx = t + i * 256;           // 0..4095
            int n = idx >> 6, qc = idx & 63;
            float4 v = *(const float4*)(Xb + (size_t)(n0 + n) * DD + qc * 4);
            unsigned h0, l0, h1, l1;
            split2(v.x, v.y, h0, l0);
            split2(v.z, v.w, h1, l1);
            *(uint2*)(Xhi + n * CPAD + qc * 4) = make_uint2(h0, h1);
            *(uint2*)(Xlo + n * CPAD + qc * 4) = make_uint2(l0, l1);
        }
        // stage W [32 o][64 n]: exp(S-m)*invl -> bf16 hi/lo
#pragma unroll
        for (int i = 0; i < 2; i++) {
            int idx = t + i * 256;           // 0..511
            int o = idx >> 4, q = idx & 15;
            float4 sv = *(const float4*)(Sb + (size_t)o * NN + n0 + q * 4);
            float w0 = __expf(sv.x - ms[o]) * ivs[o];
            float w1 = __expf(sv.y - ms[o]) * ivs[o];
            float w2 = __expf(sv.z - ms[o]) * ivs[o];
            float w3 = __expf(sv.w - ms[o]) * ivs[o];
            unsigned h0, l0, h1, l1;
            split2(w0, w1, h0, l0);
            split2(w2, w3, h1, l1);
            *(uint2*)(Whi + o * WPAD + q * 4) = make_uint2(h0, h1);
            *(uint2*)(Wlo + o * WPAD + q * 4) = make_uint2(l0, l1);
        }
        __syncthreads();

        // compute: 4 k16-steps x 8 c-tiles x 3 combos
#pragma unroll
        for (int ks = 0; ks < 4; ks++) {
            int ar = (mh * 16 + (l >> 2)) * WPAD + ks * 16 + (l & 3) * 2;
            unsigned ah[4], al[4];
            ah[0] = *(const unsigned*)(Whi + ar);
            ah[1] = *(const unsigned*)(Whi + ar + 8 * WPAD);
            ah[2] = *(const unsigned*)(Whi + ar + 8);
            ah[3] = *(const unsigned*)(Whi + ar + 8 * WPAD + 8);
            al[0] = *(const unsigned*)(Wlo + ar);
            al[1] = *(const unsigned*)(Wlo + ar + 8 * WPAD);
            al[2] = *(const unsigned*)(Wlo + ar + 8);
            al[3] = *(const unsigned*)(Wlo + ar + 8 * WPAD + 8);
            int nn = ks * 16 + (l & 3) * 2;
#pragma unroll
            for (int ct = 0; ct < 8; ct++) {
                int cc = cq * 64 + ct * 8 + (l >> 2);
                const __nv_bfloat16* ph = Xhi + nn * CPAD + cc;
                const __nv_bfloat16* pl = Xlo + nn * CPAD + cc;
                unsigned bh0 = (unsigned)*(const unsigned short*)(ph) |
                               ((unsigned)*(const unsigned short*)(ph + CPAD) << 16);
                unsigned bh1 = (unsigned)*(const unsigned short*)(ph + 8 * CPAD) |
                               ((unsigned)*(const unsigned short*)(ph + 9 * CPAD) << 16);
                unsigned bl0 = (unsigned)*(const unsigned short*)(pl) |
                               ((unsigned)*(const unsigned short*)(pl + CPAD) << 16);
                unsigned bl1 = (unsigned)*(const unsigned short*)(pl + 8 * CPAD) |
                               ((unsigned)*(const unsigned short*)(pl + 9 * CPAD) << 16);
                mma_bf16(acc[ct], ah, bh0, bh1);
                mma_bf16(acc[ct], ah, bl0, bl1);
                mma_bf16(acc[ct], al, bh0, bh1);
            }
        }
    }

    // epilogue: C[row=o][col=c] -> g_ypart[b][ns][o][ch*256 + col]
    int orow = mh * 16 + (l >> 2);
    float* yp = g_ypart + ((size_t)(b * NCH + ns) * OO) * DD + ch * 256;
#pragma unroll
    for (int ct = 0; ct < 8; ct++) {
        int col = cq * 64 + ct * 8 + 2 * (l & 3);
        yp[(size_t)orow * DD + col]           = acc[ct][0];
        yp[(size_t)orow * DD + col + 1]       = acc[ct][1];
        yp[(size_t)(orow + 8) * DD + col]     = acc[ct][2];
        yp[(size_t)(orow + 8) * DD + col + 1] = acc[ct][3];
    }
}

// ---- K4: reduce partials, apply Wv per head, Wo, residual, LayerNorm ----
__global__ __launch_bounds__(256) void k4_final(const float* __restrict__ seed,
                                                const float* __restrict__ Wv,
                                                const float* __restrict__ bv,
                                                const float* __restrict__ Wo,
                                                const float* __restrict__ bo,
                                                const float* __restrict__ gamma,
                                                const float* __restrict__ beta,
                                                float* __restrict__ out) {
    int i = blockIdx.x;
    int b = blockIdx.y;
    int t = threadIdx.x;
    __shared__ float ysh[HH * DD];
    __shared__ float presh[DD];
    __shared__ float red[256];

    for (int idx = t; idx < HH * DD; idx += 256) {
        int h = idx >> 9, c = idx & 511;
        int o = i * HH + h;
        float s = 0.f;
#pragma unroll
        for (int ch = 0; ch < NCH; ch++)
            s += g_ypart[((size_t)(b * NCH + ch) * OO + o) * DD + c];
        ysh[idx] = s;
    }
    __syncthreads();

    for (int g = t; g < DD; g += 256) {
        int h = g >> 6;
        const float4* wr = (const float4*)(Wv + (size_t)g * DD);
        const float4* yr = (const float4*)(ysh + h * DD);
        float acc = 0.f;
#pragma unroll 4
        for (int c4 = 0; c4 < DD / 4; c4++) {
            float4 w4 = wr[c4], y4 = yr[c4];
            acc += w4.x * y4.x + w4.y * y4.y + w4.z * y4.z + w4.w * y4.w;
        }
        presh[g] = acc + bv[g];
    }
    __syncthreads();

    float zv[2];
#pragma unroll
    for (int gi = 0; gi < 2; gi++) {
        int g = t + gi * 256;
        const float4* wr = (const float4*)(Wo + (size_t)g * DD);
        const float4* pr = (const float4*)presh;
        float acc = 0.f;
#pragma unroll 4
        for (int c4 = 0; c4 < DD / 4; c4++) {
            float4 w4 = wr[c4], p4 = pr[c4];
            acc += w4.x * p4.x + w4.y * p4.y + w4.z * p4.z + w4.w * p4.w;
        }
        zv[gi] = acc + bo[g] + seed[(size_t)i * DD + g];
    }

    red[t] = zv[0] + zv[1]; __syncthreads();
    for (int st = 128; st > 0; st >>= 1) { if (t < st) red[t] += red[t + st]; __syncthreads(); }
    float mu = red[0] * (1.0f / DD); __syncthreads();
    float d0 = zv[0] - mu, d1 = zv[1] - mu;
    red[t] = d0 * d0 + d1 * d1; __syncthreads();
    for (int st = 128; st > 0; st >>= 1) { if (t < st) red[t] += red[t + st]; __syncthreads(); }
    float rstd = rsqrtf(red[0] * (1.0f / DD) + 1e-6f);

    float* op = out + ((size_t)b * KSEED + i) * DD;
#pragma unroll
    for (int gi = 0; gi < 2; gi++) {
        int g = t + gi * 256;
        op[g] = (zv[gi] - mu) * rstd * gamma[g] + beta[g];
    }
}

extern "C" void kernel_launch(void* const* d_in, const int* in_sizes, int n_in,
                              void* d_out, int out_size) {
    const float* X     = (const float*)d_in[0];
    const float* seed  = (const float*)d_in[1];
    const float* Wq    = (const float*)d_in[2];
    const float* bq    = (const float*)d_in[3];
    const float* Wk    = (const float*)d_in[4];
    const float* bk    = (const float*)d_in[5];
    const float* Wv    = (const float*)d_in[6];
    const float* bv    = (const float*)d_in[7];
    const float* Wo    = (const float*)d_in[8];
    const float* bo    = (const float*)d_in[9];
    const float* gamma = (const float*)d_in[10];
    const float* beta  = (const float*)d_in[11];
    float* out = (float*)d_out;

    int k3_smem = 2 * K3_XBYTES + 2 * K3_WBYTES;   // 75776
    cudaFuncSetAttribute(k3_accum_mma, cudaFuncAttributeMaxDynamicSharedMemorySize, k3_smem);

    k0a_q<<<KSEED, DD>>>(seed, Wq, bq);
    k0b_P<<<HH, DD>>>(Wk);
    k0c_c0<<<1, 32>>>(bk);
    k1_scores_mma<<<dim3(NN / 128, BB), 256>>>(X);
    k2_stats<<<BB * OO, 256>>>();
    k3_accum_mma<<<dim3(16, BB), 256, k3_smem>>>(X);
    k4_final<<<dim3(KSEED, BB), 256>>>(seed, Wv, bv, Wo, bo, gamma, beta, out);
}

// round 8
// speedup vs baseline: 1.2103x; 1.2059x over previous
#include <cuda_runtime.h>
#include <cuda_bf16.h>
#include <math.h>
#include <stdint.h>

#define BB 16
#define NN 8192
#define DD 512
#define HH 8
#define KSEED 4
#define OO 32            // KSEED*HH, o = i*8 + h
#define NCH 8            // n-splits in K3

// ---- scratch (no allocations allowed; __device__ globals) ----
__device__ float g_q[KSEED * DD];
__device__ float g_P[OO * DD];
__device__ float g_c0[OO];
__device__ float g_S[(size_t)BB * OO * NN];        // raw scores
__device__ float g_m[BB * OO];
__device__ float g_invl[BB * OO];
__device__ float g_ypart[(size_t)BB * NCH * OO * DD];

// ---- warp-level bf16 MMA (baseline PTX, no sm_103a features needed) ----
__device__ __forceinline__ void mma_bf16(float* c, const unsigned* a,
                                         unsigned b0, unsigned b1) {
    asm volatile(
        "mma.sync.aligned.m16n8k16.row.col.f32.bf16.bf16.f32 "
        "{%0,%1,%2,%3}, {%4,%5,%6,%7}, {%8,%9}, {%0,%1,%2,%3};"
        : "+f"(c[0]), "+f"(c[1]), "+f"(c[2]), "+f"(c[3])
        : "r"(a[0]), "r"(a[1]), "r"(a[2]), "r"(a[3]), "r"(b0), "r"(b1));
}

__device__ __forceinline__ void ldsm4t(unsigned& r0, unsigned& r1,
                                       unsigned& r2, unsigned& r3,
                                       const void* p) {
    uint32_t a = (uint32_t)__cvta_generic_to_shared(p);
    asm volatile(
        "ldmatrix.sync.aligned.m8n8.x4.trans.shared.b16 {%0,%1,%2,%3}, [%4];"
        : "=r"(r0), "=r"(r1), "=r"(r2), "=r"(r3) : "r"(a));
}

// split two floats into packed bf16 hi-pair and lo-pair
__device__ __forceinline__ void split2(float a, float b, unsigned& hi, unsigned& lo) {
    __nv_bfloat16 ha = __float2bfloat16_rn(a), hb = __float2bfloat16_rn(b);
    unsigned uh = (unsigned)__bfloat16_as_ushort(ha) |
                  ((unsigned)__bfloat16_as_ushort(hb) << 16);
    __nv_bfloat16 la = __float2bfloat16_rn(a - __bfloat162float(ha));
    __nv_bfloat16 lb = __float2bfloat16_rn(b - __bfloat162float(hb));
    unsigned ul = (unsigned)__bfloat16_as_ushort(la) |
                  ((unsigned)__bfloat16_as_ushort(lb) << 16);
    hi = uh; lo = ul;
}

// ---- K0a: q[i,c] = sum_e seed[i,e]*Wq[c,e] + bq[c] ----
__global__ void k0a_q(const float* __restrict__ seed,
                      const float* __restrict__ Wq,
                      const float* __restrict__ bq) {
    int i = blockIdx.x;
    int c = threadIdx.x;
    const float4* w  = (const float4*)(Wq + (size_t)c * DD);
    const float4* sd = (const float4*)(seed + (size_t)i * DD);
    float acc = 0.f;
#pragma unroll 4
    for (int e4 = 0; e4 < DD / 4; e4++) {
        float4 a = w[e4], s4 = sd[e4];
        acc += a.x * s4.x + a.y * s4.y + a.z * s4.z + a.w * s4.w;
    }
    g_q[i * DD + c] = acc + bq[c];
}

// ---- K0b: P[(i*8+h),c] = (1/8) sum_d q[i,h*64+d] * Wk[h*64+d, c] ----
__global__ void k0b_P(const float* __restrict__ Wk) {
    __shared__ float qsh[KSEED * 64];
    int h = blockIdx.x;
    int c = threadIdx.x;
    if (c < KSEED * 64) {
        int i = c >> 6, d = c & 63;
        qsh[c] = g_q[i * DD + h * 64 + d];
    }
    __syncthreads();
    float acc[KSEED] = {0.f, 0.f, 0.f, 0.f};
    for (int d = 0; d < 64; d++) {
        float w = Wk[(size_t)(h * 64 + d) * DD + c];
#pragma unroll
        for (int i = 0; i < KSEED; i++) acc[i] += qsh[i * 64 + d] * w;
    }
#pragma unroll
    for (int i = 0; i < KSEED; i++)
        g_P[(size_t)(i * HH + h) * DD + c] = acc[i] * 0.125f;
}

// ---- K0c: c0[i*8+h] = (1/8) q[i,h*64:]·bk[h*64:] ----
__global__ void k0c_c0(const float* __restrict__ bk) {
    int t = threadIdx.x;
    if (t < OO) {
        int i = t >> 3, h = t & 7;
        float a = 0.f;
        for (int d = 0; d < 64; d++)
            a += g_q[i * DD + h * 64 + d] * bk[h * 64 + d];
        g_c0[t] = a * 0.125f;
    }
}

// ============ K1: scores[b, :, nbase..nbase+128) = X_tile @ P^T + c0 ============
// A = X rows (bf16 hi/lo), B = P (bf16 hi/lo), mma m16n8k16.
// 8 warps: warp w -> rows [w*16, w*16+16), all 4 o-tiles.
#define XP 72   // padded row (bf16 elements) for X tile
__global__ __launch_bounds__(256) void k1_scores_mma(const float* __restrict__ X) {
    __shared__ __align__(16) __nv_bfloat16 Xhi[128 * XP];
    __shared__ __align__(16) __nv_bfloat16 Xlo[128 * XP];
    __shared__ __align__(16) __nv_bfloat16 Phi[OO * XP];
    __shared__ __align__(16) __nv_bfloat16 Plo[OO * XP];
    __shared__ float c0s[OO];

    int t = threadIdx.x, w = t >> 5, l = t & 31;
    int b = blockIdx.y;
    int nbase = blockIdx.x * 128;
    if (t < OO) c0s[t] = g_c0[t];

    float acc[4][4];
#pragma unroll
    for (int ot = 0; ot < 4; ot++)
#pragma unroll
        for (int j = 0; j < 4; j++) acc[ot][j] = 0.f;

    const float* Xb = X + ((size_t)b * NN + nbase) * DD;

#pragma unroll 1
    for (int kc = 0; kc < 8; kc++) {
        int cbase = kc * 64;
        float4 xv[8], pv[2];
#pragma unroll
        for (int i = 0; i < 8; i++) {
            int idx = t + i * 256;
            int row = idx >> 4, q = idx & 15;
            xv[i] = *(const float4*)(Xb + (size_t)row * DD + cbase + q * 4);
        }
#pragma unroll
        for (int i = 0; i < 2; i++) {
            int idx = t + i * 256;
            int row = idx >> 4, q = idx & 15;
            pv[i] = *(const float4*)(g_P + (size_t)row * DD + cbase + q * 4);
        }
        __syncthreads();
#pragma unroll
        for (int i = 0; i < 8; i++) {
            int idx = t + i * 256;
            int row = idx >> 4, q = idx & 15;
            unsigned h0, l0, h1, l1;
            split2(xv[i].x, xv[i].y, h0, l0);
            split2(xv[i].z, xv[i].w, h1, l1);
            *(uint2*)(Xhi + row * XP + q * 4) = make_uint2(h0, h1);
            *(uint2*)(Xlo + row * XP + q * 4) = make_uint2(l0, l1);
        }
#pragma unroll
        for (int i = 0; i < 2; i++) {
            int idx = t + i * 256;
            int row = idx >> 4, q = idx & 15;
            unsigned h0, l0, h1, l1;
            split2(pv[i].x, pv[i].y, h0, l0);
            split2(pv[i].z, pv[i].w, h1, l1);
            *(uint2*)(Phi + row * XP + q * 4) = make_uint2(h0, h1);
            *(uint2*)(Plo + row * XP + q * 4) = make_uint2(l0, l1);
        }
        __syncthreads();

#pragma unroll
        for (int ks = 0; ks < 4; ks++) {
            int ar = (w * 16 + (l >> 2)) * XP + ks * 16 + (l & 3) * 2;
            unsigned ah[4], al[4];
            ah[0] = *(const unsigned*)(Xhi + ar);
            ah[1] = *(const unsigned*)(Xhi + ar + 8 * XP);
            ah[2] = *(const unsigned*)(Xhi + ar + 8);
            ah[3] = *(const unsigned*)(Xhi + ar + 8 * XP + 8);
            al[0] = *(const unsigned*)(Xlo + ar);
            al[1] = *(const unsigned*)(Xlo + ar + 8 * XP);
            al[2] = *(const unsigned*)(Xlo + ar + 8);
            al[3] = *(const unsigned*)(Xlo + ar + 8 * XP + 8);
#pragma unroll
            for (int ot = 0; ot < 4; ot++) {
                int br = (ot * 8 + (l >> 2)) * XP + ks * 16 + (l & 3) * 2;
                unsigned bh0 = *(const unsigned*)(Phi + br);
                unsigned bh1 = *(const unsigned*)(Phi + br + 8);
                unsigned bl0 = *(const unsigned*)(Plo + br);
                unsigned bl1 = *(const unsigned*)(Plo + br + 8);
                mma_bf16(acc[ot], ah, bh0, bh1);
                mma_bf16(acc[ot], ah, bl0, bl1);
                mma_bf16(acc[ot], al, bh0, bh1);
            }
        }
    }

    int row = w * 16 + (l >> 2);
    int n = nbase + row;
#pragma unroll
    for (int ot = 0; ot < 4; ot++) {
        int col = ot * 8 + 2 * (l & 3);
        g_S[((size_t)b * OO + col)     * NN + n]     = acc[ot][0] + c0s[col];
        g_S[((size_t)b * OO + col + 1) * NN + n]     = acc[ot][1] + c0s[col + 1];
        g_S[((size_t)b * OO + col)     * NN + n + 8] = acc[ot][2] + c0s[col];
        g_S[((size_t)b * OO + col + 1) * NN + n + 8] = acc[ot][3] + c0s[col + 1];
    }
}

// ---- K2: stats per (b,o): m = max, invl = 1/sum exp(s-m) ----
__global__ __launch_bounds__(256) void k2_stats() {
    int bo = blockIdx.x;
    const float4* s4 = (const float4*)(g_S + (size_t)bo * NN);
    int t = threadIdx.x;
    __shared__ float red[256];
    float m = -1e30f;
    for (int q = t; q < NN / 4; q += 256) {
        float4 v = s4[q];
        m = fmaxf(m, fmaxf(fmaxf(v.x, v.y), fmaxf(v.z, v.w)));
    }
    red[t] = m; __syncthreads();
    for (int st = 128; st > 0; st >>= 1) {
        if (t < st) red[t] = fmaxf(red[t], red[t + st]);
        __syncthreads();
    }
    m = red[0]; __syncthreads();
    float sum = 0.f;
    for (int q = t; q < NN / 4; q += 256) {
        float4 v = s4[q];
        sum += __expf(v.x - m) + __expf(v.y - m) + __expf(v.z - m) + __expf(v.w - m);
    }
    red[t] = sum; __syncthreads();
    for (int st = 128; st > 0; st >>= 1) {
        if (t < st) red[t] += red[t + st];
        __syncthreads();
    }
    if (t == 0) { g_m[bo] = m; g_invl[bo] = 1.0f / red[0]; }
}

// ============ K3: Y[b,ns][o][c] = sum_{n in ns} w[b,o,n] * X[b,n,c] ============
// A = W (bf16 hi/lo, [o][n] from g_S + exp transform), scalar frag loads.
// B = X (bf16 hi/lo, [n][c]), fragments via ldmatrix.m8n8.x4.trans.
// grid.x = 16: ns = bx>>1 (n-eighth of 1024), ch = bx&1 (c-half of 256).
// 8 warps: mh = w>>2 (o-half of 16), cq = w&3 (64-c quarter). acc 8 c-tiles.
#define CPAD 264   // X chunk row stride (bf16) — 528 B: 16B-aligned rows, conflict-free ldsm
#define WPAD 72
#define K3_XBYTES (64 * CPAD * 2)      // 33792
#define K3_WBYTES (OO * WPAD * 2)      // 4608
__global__ __launch_bounds__(256) void k3_accum_mma(const float* __restrict__ X) {
    extern __shared__ __align__(16) char sm3[];
    __nv_bfloat16* Xhi = (__nv_bfloat16*)(sm3);
    __nv_bfloat16* Xlo = (__nv_bfloat16*)(sm3 + K3_XBYTES);
    __nv_bfloat16* Whi = (__nv_bfloat16*)(sm3 + 2 * K3_XBYTES);
    __nv_bfloat16* Wlo = (__nv_bfloat16*)(sm3 + 2 * K3_XBYTES + K3_WBYTES);
    __shared__ float ms[OO], ivs[OO];

    int t = threadIdx.x, w = t >> 5, l = t & 31;
    int b = blockIdx.y;
    int ns = blockIdx.x >> 1;
    int ch = blockIdx.x & 1;
    int mh = w >> 2, cq = w & 3;

    if (t < OO) { ms[t] = g_m[b * OO + t]; ivs[t] = g_invl[b * OO + t]; }

    float acc[8][4];
#pragma unroll
    for (int ct = 0; ct < 8; ct++)
#pragma unroll
        for (int j = 0; j < 4; j++) acc[ct][j] = 0.f;

    const float* Xb = X + (size_t)b * NN * DD + ch * 256;
    const float* Sb = g_S + (size_t)b * OO * NN;

    // per-lane ldmatrix source offsets (within a ks/cp tile)
    int lm_row = ((l >> 3) & 1) * 8 + (l & 7);   // k-row within 16
    int lm_col = (l >> 4) * 8;                   // +8 cols for lanes 16-31

#pragma unroll 1
    for (int s = 0; s < 16; s++) {
        int n0 = ns * 1024 + s * 64;
        __syncthreads();
        // stage X [64 n][256 c] fp32 -> bf16 hi/lo
#pragma unroll 4
        for (int i = 0; i < 16; i++) {
            int idx = t + i * 256;
            int n = idx >> 6, qc = idx & 63;
            float4 v = *(const float4*)(Xb + (size_t)(n0 + n) * DD + qc * 4);
            unsigned h0, l0, h1, l1;
            split2(v.x, v.y, h0, l0);
            split2(v.z, v.w, h1, l1);
            *(uint2*)(Xhi + n * CPAD + qc * 4) = make_uint2(h0, h1);
            *(uint2*)(Xlo + n * CPAD + qc * 4) = make_uint2(l0, l1);
        }
        // stage W [32 o][64 n]: exp(S-m)*invl -> bf16 hi/lo
#pragma unroll
        for (int i = 0; i < 2; i++) {
            int idx = t + i * 256;
            int o = idx >> 4, q = idx & 15;
            float4 sv = *(const float4*)(Sb + (size_t)o * NN + n0 + q * 4);
            float w0 = __expf(sv.x - ms[o]) * ivs[o];
            float w1 = __expf(sv.y - ms[o]) * ivs[o];
            float w2 = __expf(sv.z - ms[o]) * ivs[o];
            float w3 = __expf(sv.w - ms[o]) * ivs[o];
            unsigned h0, l0, h1, l1;
            split2(w0, w1, h0, l0);
            split2(w2, w3, h1, l1);
            *(uint2*)(Whi + o * WPAD + q * 4) = make_uint2(h0, h1);
            *(uint2*)(Wlo + o * WPAD + q * 4) = make_uint2(l0, l1);
        }
        __syncthreads();

        // compute: 4 k16-steps x 4 c-tile-pairs x 3 combos
#pragma unroll
        for (int ks = 0; ks < 4; ks++) {
            int ar = (mh * 16 + (l >> 2)) * WPAD + ks * 16 + (l & 3) * 2;
            unsigned ah[4], al[4];
            ah[0] = *(const unsigned*)(Whi + ar);
            ah[1] = *(const unsigned*)(Whi + ar + 8 * WPAD);
            ah[2] = *(const unsigned*)(Whi + ar + 8);
            ah[3] = *(const unsigned*)(Whi + ar + 8 * WPAD + 8);
            al[0] = *(const unsigned*)(Wlo + ar);
            al[1] = *(const unsigned*)(Wlo + ar + 8 * WPAD);
            al[2] = *(const unsigned*)(Wlo + ar + 8);
            al[3] = *(const unsigned*)(Wlo + ar + 8 * WPAD + 8);
            int nr = (ks * 16 + lm_row) * CPAD;
#pragma unroll
            for (int cp = 0; cp < 4; cp++) {
                int cc = cq * 64 + cp * 16 + lm_col;
                unsigned bh0, bh1, bh2, bh3, bl0, bl1, bl2, bl3;
                ldsm4t(bh0, bh1, bh2, bh3, Xhi + nr + cc);
                ldsm4t(bl0, bl1, bl2, bl3, Xlo + nr + cc);
                mma_bf16(acc[2 * cp],     ah, bh0, bh1);
                mma_bf16(acc[2 * cp],     ah, bl0, bl1);
                mma_bf16(acc[2 * cp],     al, bh0, bh1);
                mma_bf16(acc[2 * cp + 1], ah, bh2, bh3);
                mma_bf16(acc[2 * cp + 1], ah, bl2, bl3);
                mma_bf16(acc[2 * cp + 1], al, bh2, bh3);
            }
        }
    }

    // epilogue: C[row=o][col=c] -> g_ypart[b][ns][o][ch*256 + col]
    int orow = mh * 16 + (l >> 2);
    float* yp = g_ypart + ((size_t)(b * NCH + ns) * OO) * DD + ch * 256;
#pragma unroll
    for (int ct = 0; ct < 8; ct++) {
        int col = cq * 64 + (ct >> 1) * 16 + (ct & 1) * 8 + 2 * (l & 3);
        yp[(size_t)orow * DD + col]           = acc[ct][0];
        yp[(size_t)orow * DD + col + 1]       = acc[ct][1];
        yp[(size_t)(orow + 8) * DD + col]     = acc[ct][2];
        yp[(size_t)(orow + 8) * DD + col + 1] = acc[ct][3];
    }
}

// ---- K4: reduce partials, apply Wv per head, Wo, residual, LayerNorm ----
__global__ __launch_bounds__(256) void k4_final(const float* __restrict__ seed,
                                                const float* __restrict__ Wv,
                                                const float* __restrict__ bv,
                                                const float* __restrict__ Wo,
                                                const float* __restrict__ bo,
                                                const float* __restrict__ gamma,
                                                const float* __restrict__ beta,
                                                float* __restrict__ out) {
    int i = blockIdx.x;
    int b = blockIdx.y;
    int t = threadIdx.x;
    __shared__ float ysh[HH * DD];
    __shared__ float presh[DD];
    __shared__ float red[256];

    for (int idx = t; idx < HH * DD; idx += 256) {
        int h = idx >> 9, c = idx & 511;
        int o = i * HH + h;
        float s = 0.f;
#pragma unroll
        for (int ch = 0; ch < NCH; ch++)
            s += g_ypart[((size_t)(b * NCH + ch) * OO + o) * DD + c];
        ysh[idx] = s;
    }
    __syncthreads();

    for (int g = t; g < DD; g += 256) {
        int h = g >> 6;
        const float4* wr = (const float4*)(Wv + (size_t)g * DD);
        const float4* yr = (const float4*)(ysh + h * DD);
        float acc = 0.f;
#pragma unroll 4
        for (int c4 = 0; c4 < DD / 4; c4++) {
            float4 w4 = wr[c4], y4 = yr[c4];
            acc += w4.x * y4.x + w4.y * y4.y + w4.z * y4.z + w4.w * y4.w;
        }
        presh[g] = acc + bv[g];
    }
    __syncthreads();

    float zv[2];
#pragma unroll
    for (int gi = 0; gi < 2; gi++) {
        int g = t + gi * 256;
        const float4* wr = (const float4*)(Wo + (size_t)g * DD);
        const float4* pr = (const float4*)presh;
        float acc = 0.f;
#pragma unroll 4
        for (int c4 = 0; c4 < DD / 4; c4++) {
            float4 w4 = wr[c4], p4 = pr[c4];
            acc += w4.x * p4.x + w4.y * p4.y + w4.z * p4.z + w4.w * p4.w;
        }
        zv[gi] = acc + bo[g] + seed[(size_t)i * DD + g];
    }

    red[t] = zv[0] + zv[1]; __syncthreads();
    for (int st = 128; st > 0; st >>= 1) { if (t < st) red[t] += red[t + st]; __syncthreads(); }
    float mu = red[0] * (1.0f / DD); __syncthreads();
    float d0 = zv[0] - mu, d1 = zv[1] - mu;
    red[t] = d0 * d0 + d1 * d1; __syncthreads();
    for (int st = 128; st > 0; st >>= 1) { if (t < st) red[t] += red[t + st]; __syncthreads(); }
    float rstd = rsqrtf(red[0] * (1.0f / DD) + 1e-6f);

    float* op = out + ((size_t)b * KSEED + i) * DD;
#pragma unroll
    for (int gi = 0; gi < 2; gi++) {
        int g = t + gi * 256;
        op[g] = (zv[gi] - mu) * rstd * gamma[g] + beta[g];
    }
}

extern "C" void kernel_launch(void* const* d_in, const int* in_sizes, int n_in,
                              void* d_out, int out_size) {
    const float* X     = (const float*)d_in[0];
    const float* seed  = (const float*)d_in[1];
    const float* Wq    = (const float*)d_in[2];
    const float* bq    = (const float*)d_in[3];
    const float* Wk    = (const float*)d_in[4];
    const float* bk    = (const float*)d_in[5];
    const float* Wv    = (const float*)d_in[6];
    const float* bv    = (const float*)d_in[7];
    const float* Wo    = (const float*)d_in[8];
    const float* bo    = (const float*)d_in[9];
    const float* gamma = (const float*)d_in[10];
    const float* beta  = (const float*)d_in[11];
    float* out = (float*)d_out;

    int k3_smem = 2 * K3_XBYTES + 2 * K3_WBYTES;   // 76800
    cudaFuncSetAttribute(k3_accum_mma, cudaFuncAttributeMaxDynamicSharedMemorySize, k3_smem);

    k0a_q<<<KSEED, DD>>>(seed, Wq, bq);
    k0b_P<<<HH, DD>>>(Wk);
    k0c_c0<<<1, 32>>>(bk);
    k1_scores_mma<<<dim3(NN / 128, BB), 256>>>(X);
    k2_stats<<<BB * OO, 256>>>();
    k3_accum_mma<<<dim3(16, BB), 256, k3_smem>>>(X);
    k4_final<<<dim3(KSEED, BB), 256>>>(seed, Wv, bv, Wo, bo, gamma, beta, out);
}

// round 9
// speedup vs baseline: 1.2374x; 1.0223x over previous
#include <cuda_runtime.h>
#include <cuda_bf16.h>
#include <math.h>
#include <stdint.h>

#define BB 16
#define NN 8192
#define DD 512
#define HH 8
#define KSEED 4
#define OO 32            // KSEED*HH, o = i*8 + h
#define NCH 8            // n-splits in K3

// ---- scratch (no allocations allowed; __device__ globals) ----
__device__ float g_q[KSEED * DD];
__device__ float g_P[OO * DD];
__device__ float g_c0[OO];
__device__ float g_S[(size_t)BB * OO * NN];        // raw scores
__device__ float g_m[BB * OO];
__device__ float g_invl[BB * OO];
__device__ float g_ypart[(size_t)BB * NCH * OO * DD];

// ---- warp-level bf16 MMA (baseline PTX, no sm_103a features needed) ----
__device__ __forceinline__ void mma_bf16(float* c, const unsigned* a,
                                         unsigned b0, unsigned b1) {
    asm volatile(
        "mma.sync.aligned.m16n8k16.row.col.f32.bf16.bf16.f32 "
        "{%0,%1,%2,%3}, {%4,%5,%6,%7}, {%8,%9}, {%0,%1,%2,%3};"
        : "+f"(c[0]), "+f"(c[1]), "+f"(c[2]), "+f"(c[3])
        : "r"(a[0]), "r"(a[1]), "r"(a[2]), "r"(a[3]), "r"(b0), "r"(b1));
}

__device__ __forceinline__ void ldsm4t(unsigned& r0, unsigned& r1,
                                       unsigned& r2, unsigned& r3,
                                       const void* p) {
    uint32_t a = (uint32_t)__cvta_generic_to_shared(p);
    asm volatile(
        "ldmatrix.sync.aligned.m8n8.x4.trans.shared.b16 {%0,%1,%2,%3}, [%4];"
        : "=r"(r0), "=r"(r1), "=r"(r2), "=r"(r3) : "r"(a));
}

// split two floats into packed bf16 hi-pair and lo-pair
__device__ __forceinline__ void split2(float a, float b, unsigned& hi, unsigned& lo) {
    __nv_bfloat16 ha = __float2bfloat16_rn(a), hb = __float2bfloat16_rn(b);
    unsigned uh = (unsigned)__bfloat16_as_ushort(ha) |
                  ((unsigned)__bfloat16_as_ushort(hb) << 16);
    __nv_bfloat16 la = __float2bfloat16_rn(a - __bfloat162float(ha));
    __nv_bfloat16 lb = __float2bfloat16_rn(b - __bfloat162float(hb));
    unsigned ul = (unsigned)__bfloat16_as_ushort(la) |
                  ((unsigned)__bfloat16_as_ushort(lb) << 16);
    hi = uh; lo = ul;
}

// ---- K0a: q[i,c] = sum_e seed[i,e]*Wq[c,e] + bq[c] ----
__global__ void k0a_q(const float* __restrict__ seed,
                      const float* __restrict__ Wq,
                      const float* __restrict__ bq) {
    int i = blockIdx.x;
    int c = threadIdx.x;
    const float4* w  = (const float4*)(Wq + (size_t)c * DD);
    const float4* sd = (const float4*)(seed + (size_t)i * DD);
    float acc = 0.f;
#pragma unroll 4
    for (int e4 = 0; e4 < DD / 4; e4++) {
        float4 a = w[e4], s4 = sd[e4];
        acc += a.x * s4.x + a.y * s4.y + a.z * s4.z + a.w * s4.w;
    }
    g_q[i * DD + c] = acc + bq[c];
}

// ---- K0b: P[(i*8+h),c] = (1/8) sum_d q[i,h*64+d] * Wk[h*64+d, c] ----
__global__ void k0b_P(const float* __restrict__ Wk) {
    __shared__ float qsh[KSEED * 64];
    int h = blockIdx.x;
    int c = threadIdx.x;
    if (c < KSEED * 64) {
        int i = c >> 6, d = c & 63;
        qsh[c] = g_q[i * DD + h * 64 + d];
    }
    __syncthreads();
    float acc[KSEED] = {0.f, 0.f, 0.f, 0.f};
    for (int d = 0; d < 64; d++) {
        float w = Wk[(size_t)(h * 64 + d) * DD + c];
#pragma unroll
        for (int i = 0; i < KSEED; i++) acc[i] += qsh[i * 64 + d] * w;
    }
#pragma unroll
    for (int i = 0; i < KSEED; i++)
        g_P[(size_t)(i * HH + h) * DD + c] = acc[i] * 0.125f;
}

// ---- K0c: c0[i*8+h] = (1/8) q[i,h*64:]·bk[h*64:] ----
__global__ void k0c_c0(const float* __restrict__ bk) {
    int t = threadIdx.x;
    if (t < OO) {
        int i = t >> 3, h = t & 7;
        float a = 0.f;
        for (int d = 0; d < 64; d++)
            a += g_q[i * DD + h * 64 + d] * bk[h * 64 + d];
        g_c0[t] = a * 0.125f;
    }
}

// ============ K1: scores[b, :, nbase..nbase+128) = X_tile @ P^T + c0 ============
#define XP 72   // padded row (bf16 elements) for X tile
__global__ __launch_bounds__(256) void k1_scores_mma(const float* __restrict__ X) {
    __shared__ __align__(16) __nv_bfloat16 Xhi[128 * XP];
    __shared__ __align__(16) __nv_bfloat16 Xlo[128 * XP];
    __shared__ __align__(16) __nv_bfloat16 Phi[OO * XP];
    __shared__ __align__(16) __nv_bfloat16 Plo[OO * XP];
    __shared__ float c0s[OO];

    int t = threadIdx.x, w = t >> 5, l = t & 31;
    int b = blockIdx.y;
    int nbase = blockIdx.x * 128;
    if (t < OO) c0s[t] = g_c0[t];

    float acc[4][4];
#pragma unroll
    for (int ot = 0; ot < 4; ot++)
#pragma unroll
        for (int j = 0; j < 4; j++) acc[ot][j] = 0.f;

    const float* Xb = X + ((size_t)b * NN + nbase) * DD;

#pragma unroll 1
    for (int kc = 0; kc < 8; kc++) {
        int cbase = kc * 64;
        float4 xv[8], pv[2];
#pragma unroll
        for (int i = 0; i < 8; i++) {
            int idx = t + i * 256;
            int row = idx >> 4, q = idx & 15;
            xv[i] = *(const float4*)(Xb + (size_t)row * DD + cbase + q * 4);
        }
#pragma unroll
        for (int i = 0; i < 2; i++) {
            int idx = t + i * 256;
            int row = idx >> 4, q = idx & 15;
            pv[i] = *(const float4*)(g_P + (size_t)row * DD + cbase + q * 4);
        }
        __syncthreads();
#pragma unroll
        for (int i = 0; i < 8; i++) {
            int idx = t + i * 256;
            int row = idx >> 4, q = idx & 15;
            unsigned h0, l0, h1, l1;
            split2(xv[i].x, xv[i].y, h0, l0);
            split2(xv[i].z, xv[i].w, h1, l1);
            *(uint2*)(Xhi + row * XP + q * 4) = make_uint2(h0, h1);
            *(uint2*)(Xlo + row * XP + q * 4) = make_uint2(l0, l1);
        }
#pragma unroll
        for (int i = 0; i < 2; i++) {
            int idx = t + i * 256;
            int row = idx >> 4, q = idx & 15;
            unsigned h0, l0, h1, l1;
            split2(pv[i].x, pv[i].y, h0, l0);
            split2(pv[i].z, pv[i].w, h1, l1);
            *(uint2*)(Phi + row * XP + q * 4) = make_uint2(h0, h1);
            *(uint2*)(Plo + row * XP + q * 4) = make_uint2(l0, l1);
        }
        __syncthreads();

#pragma unroll
        for (int ks = 0; ks < 4; ks++) {
            int ar = (w * 16 + (l >> 2)) * XP + ks * 16 + (l & 3) * 2;
            unsigned ah[4], al[4];
            ah[0] = *(const unsigned*)(Xhi + ar);
            ah[1] = *(const unsigned*)(Xhi + ar + 8 * XP);
            ah[2] = *(const unsigned*)(Xhi + ar + 8);
            ah[3] = *(const unsigned*)(Xhi + ar + 8 * XP + 8);
            al[0] = *(const unsigned*)(Xlo + ar);
            al[1] = *(const unsigned*)(Xlo + ar + 8 * XP);
            al[2] = *(const unsigned*)(Xlo + ar + 8);
            al[3] = *(const unsigned*)(Xlo + ar + 8 * XP + 8);
#pragma unroll
            for (int ot = 0; ot < 4; ot++) {
                int br = (ot * 8 + (l >> 2)) * XP + ks * 16 + (l & 3) * 2;
                unsigned bh0 = *(const unsigned*)(Phi + br);
                unsigned bh1 = *(const unsigned*)(Phi + br + 8);
                unsigned bl0 = *(const unsigned*)(Plo + br);
                unsigned bl1 = *(const unsigned*)(Plo + br + 8);
                mma_bf16(acc[ot], ah, bh0, bh1);
                mma_bf16(acc[ot], ah, bl0, bl1);
                mma_bf16(acc[ot], al, bh0, bh1);
            }
        }
    }

    int row = w * 16 + (l >> 2);
    int n = nbase + row;
#pragma unroll
    for (int ot = 0; ot < 4; ot++) {
        int col = ot * 8 + 2 * (l & 3);
        g_S[((size_t)b * OO + col)     * NN + n]     = acc[ot][0] + c0s[col];
        g_S[((size_t)b * OO + col + 1) * NN + n]     = acc[ot][1] + c0s[col + 1];
        g_S[((size_t)b * OO + col)     * NN + n + 8] = acc[ot][2] + c0s[col];
        g_S[((size_t)b * OO + col + 1) * NN + n + 8] = acc[ot][3] + c0s[col + 1];
    }
}

// ---- K2: stats per (b,o): m = max, invl = 1/sum exp(s-m) ----
__global__ __launch_bounds__(256) void k2_stats() {
    int bo = blockIdx.x;
    const float4* s4 = (const float4*)(g_S + (size_t)bo * NN);
    int t = threadIdx.x;
    __shared__ float red[256];
    float m = -1e30f;
    for (int q = t; q < NN / 4; q += 256) {
        float4 v = s4[q];
        m = fmaxf(m, fmaxf(fmaxf(v.x, v.y), fmaxf(v.z, v.w)));
    }
    red[t] = m; __syncthreads();
    for (int st = 128; st > 0; st >>= 1) {
        if (t < st) red[t] = fmaxf(red[t], red[t + st]);
        __syncthreads();
    }
    m = red[0]; __syncthreads();
    float sum = 0.f;
    for (int q = t; q < NN / 4; q += 256) {
        float4 v = s4[q];
        sum += __expf(v.x - m) + __expf(v.y - m) + __expf(v.z - m) + __expf(v.w - m);
    }
    red[t] = sum; __syncthreads();
    for (int st = 128; st > 0; st >>= 1) {
        if (t < st) red[t] += red[t + st];
        __syncthreads();
    }
    if (t == 0) { g_m[bo] = m; g_invl[bo] = 1.0f / red[0]; }
}

// ============ K3: Y[b,ns][o][c] = sum_{n in ns} w[b,o,n] * X[b,n,c] ============
// grid.x = 32: ns = bx>>2 (1024-n eighth), cq = bx&3 (128-c quarter).
// Small tile => ~44 KB static smem, 3 CTAs/SM, inter-CTA latency hiding (K1-style).
// 8 warps: mh = w>>2 (o-half of 16 rows), wc = w&3 (32-c slice). acc 4 c-tiles.
#define CPAD3 136   // 272 B row: 16B-aligned, conflict-free ldsm (68 words % 32 = 4)
#define WPAD 72
__global__ __launch_bounds__(256) void k3_accum_mma(const float* __restrict__ X) {
    __shared__ __align__(16) __nv_bfloat16 Xhi3[64 * CPAD3];
    __shared__ __align__(16) __nv_bfloat16 Xlo3[64 * CPAD3];
    __shared__ __align__(16) __nv_bfloat16 Whi[OO * WPAD];
    __shared__ __align__(16) __nv_bfloat16 Wlo[OO * WPAD];
    __shared__ float ms[OO], ivs[OO];

    int t = threadIdx.x, w = t >> 5, l = t & 31;
    int b = blockIdx.y;
    int ns = blockIdx.x >> 2;
    int cq = blockIdx.x & 3;
    int mh = w >> 2, wc = w & 3;

    if (t < OO) { ms[t] = g_m[b * OO + t]; ivs[t] = g_invl[b * OO + t]; }

    float acc[4][4];
#pragma unroll
    for (int ct = 0; ct < 4; ct++)
#pragma unroll
        for (int j = 0; j < 4; j++) acc[ct][j] = 0.f;

    const float* Xb = X + (size_t)b * NN * DD + cq * 128;
    const float* Sb = g_S + (size_t)b * OO * NN;

    int lm_row = ((l >> 3) & 1) * 8 + (l & 7);
    int lm_col = (l >> 4) * 8;

#pragma unroll 1
    for (int s = 0; s < 16; s++) {
        int n0 = ns * 1024 + s * 64;
        __syncthreads();
        // stage X [64 n][128 c] fp32 -> bf16 hi/lo
#pragma unroll
        for (int i = 0; i < 8; i++) {
            int idx = t + i * 256;           // 0..2047
            int n = idx >> 5, qc = idx & 31;
            float4 v = *(const float4*)(Xb + (size_t)(n0 + n) * DD + qc * 4);
            unsigned h0, l0, h1, l1;
            split2(v.x, v.y, h0, l0);
            split2(v.z, v.w, h1, l1);
            *(uint2*)(Xhi3 + n * CPAD3 + qc * 4) = make_uint2(h0, h1);
            *(uint2*)(Xlo3 + n * CPAD3 + qc * 4) = make_uint2(l0, l1);
        }
        // stage W [32 o][64 n]: exp(S-m)*invl -> bf16 hi/lo
#pragma unroll
        for (int i = 0; i < 2; i++) {
            int idx = t + i * 256;
            int o = idx >> 4, q = idx & 15;
            float4 sv = *(const float4*)(Sb + (size_t)o * NN + n0 + q * 4);
            float w0 = __expf(sv.x - ms[o]) * ivs[o];
            float w1 = __expf(sv.y - ms[o]) * ivs[o];
            float w2 = __expf(sv.z - ms[o]) * ivs[o];
            float w3 = __expf(sv.w - ms[o]) * ivs[o];
            unsigned h0, l0, h1, l1;
            split2(w0, w1, h0, l0);
            split2(w2, w3, h1, l1);
            *(uint2*)(Whi + o * WPAD + q * 4) = make_uint2(h0, h1);
            *(uint2*)(Wlo + o * WPAD + q * 4) = make_uint2(l0, l1);
        }
        __syncthreads();

        // compute: 4 k16-steps x 2 c-tile-pairs x 3 combos
#pragma unroll
        for (int ks = 0; ks < 4; ks++) {
            int ar = (mh * 16 + (l >> 2)) * WPAD + ks * 16 + (l & 3) * 2;
            unsigned ah[4], al[4];
            ah[0] = *(const unsigned*)(Whi + ar);
            ah[1] = *(const unsigned*)(Whi + ar + 8 * WPAD);
            ah[2] = *(const unsigned*)(Whi + ar + 8);
            ah[3] = *(const unsigned*)(Whi + ar + 8 * WPAD + 8);
            al[0] = *(const unsigned*)(Wlo + ar);
            al[1] = *(const unsigned*)(Wlo + ar + 8 * WPAD);
            al[2] = *(const unsigned*)(Wlo + ar + 8);
            al[3] = *(const unsigned*)(Wlo + ar + 8 * WPAD + 8);
            int nr = (ks * 16 + lm_row) * CPAD3;
#pragma unroll
            for (int cp = 0; cp < 2; cp++) {
                int cc = wc * 32 + cp * 16 + lm_col;
                unsigned bh0, bh1, bh2, bh3, bl0, bl1, bl2, bl3;
                ldsm4t(bh0, bh1, bh2, bh3, Xhi3 + nr + cc);
                ldsm4t(bl0, bl1, bl2, bl3, Xlo3 + nr + cc);
                mma_bf16(acc[2 * cp],     ah, bh0, bh1);
                mma_bf16(acc[2 * cp],     ah, bl0, bl1);
                mma_bf16(acc[2 * cp],     al, bh0, bh1);
                mma_bf16(acc[2 * cp + 1], ah, bh2, bh3);
                mma_bf16(acc[2 * cp + 1], ah, bl2, bl3);
                mma_bf16(acc[2 * cp + 1], al, bh2, bh3);
            }
        }
    }

    // epilogue: C[row=o][col=c] -> g_ypart[b][ns][o][cq*128 + col]
    int orow = mh * 16 + (l >> 2);
    float* yp = g_ypart + ((size_t)(b * NCH + ns) * OO) * DD + cq * 128;
#pragma unroll
    for (int ct = 0; ct < 4; ct++) {
        int col = wc * 32 + (ct >> 1) * 16 + (ct & 1) * 8 + 2 * (l & 3);
        yp[(size_t)orow * DD + col]           = acc[ct][0];
        yp[(size_t)orow * DD + col + 1]       = acc[ct][1];
        yp[(size_t)(orow + 8) * DD + col]     = acc[ct][2];
        yp[(size_t)(orow + 8) * DD + col + 1] = acc[ct][3];
    }
}

// ---- K4: reduce partials, apply Wv per head, Wo, residual, LayerNorm ----
__global__ __launch_bounds__(256) void k4_final(const float* __restrict__ seed,
                                                const float* __restrict__ Wv,
                                                const float* __restrict__ bv,
                                                const float* __restrict__ Wo,
                                                const float* __restrict__ bo,
                                                const float* __restrict__ gamma,
                                                const float* __restrict__ beta,
                                                float* __restrict__ out) {
    int i = blockIdx.x;
    int b = blockIdx.y;
    int t = threadIdx.x;
    __shared__ float ysh[HH * DD];
    __shared__ float presh[DD];
    __shared__ float red[256];

    for (int idx = t; idx < HH * DD; idx += 256) {
        int h = idx >> 9, c = idx & 511;
        int o = i * HH + h;
        float s = 0.f;
#pragma unroll
        for (int ch = 0; ch < NCH; ch++)
            s += g_ypart[((size_t)(b * NCH + ch) * OO + o) * DD + c];
        ysh[idx] = s;
    }
    __syncthreads();

    for (int g = t; g < DD; g += 256) {
        int h = g >> 6;
        const float4* wr = (const float4*)(Wv + (size_t)g * DD);
        const float4* yr = (const float4*)(ysh + h * DD);
        float acc = 0.f;
#pragma unroll 4
        for (int c4 = 0; c4 < DD / 4; c4++) {
            float4 w4 = wr[c4], y4 = yr[c4];
            acc += w4.x * y4.x + w4.y * y4.y + w4.z * y4.z + w4.w * y4.w;
        }
        presh[g] = acc + bv[g];
    }
    __syncthreads();

    float zv[2];
#pragma unroll
    for (int gi = 0; gi < 2; gi++) {
        int g = t + gi * 256;
        const float4* wr = (const float4*)(Wo + (size_t)g * DD);
        const float4* pr = (const float4*)presh;
        float acc = 0.f;
#pragma unroll 4
        for (int c4 = 0; c4 < DD / 4; c4++) {
            float4 w4 = wr[c4], p4 = pr[c4];
            acc += w4.x * p4.x + w4.y * p4.y + w4.z * p4.z + w4.w * p4.w;
        }
        zv[gi] = acc + bo[g] + seed[(size_t)i * DD + g];
    }

    red[t] = zv[0] + zv[1]; __syncthreads();
    for (int st = 128; st > 0; st >>= 1) { if (t < st) red[t] += red[t + st]; __syncthreads(); }
    float mu = red[0] * (1.0f / DD); __syncthreads();
    float d0 = zv[0] - mu, d1 = zv[1] - mu;
    red[t] = d0 * d0 + d1 * d1; __syncthreads();
    for (int st = 128; st > 0; st >>= 1) { if (t < st) red[t] += red[t + st]; __syncthreads(); }
    float rstd = rsqrtf(red[0] * (1.0f / DD) + 1e-6f);

    float* op = out + ((size_t)b * KSEED + i) * DD;
#pragma unroll
    for (int gi = 0; gi < 2; gi++) {
        int g = t + gi * 256;
        op[g] = (zv[gi] - mu) * rstd * gamma[g] + beta[g];
    }
}

extern "C" void kernel_launch(void* const* d_in, const int* in_sizes, int n_in,
                              void* d_out, int out_size) {
    const float* X     = (const float*)d_in[0];
    const float* seed  = (const float*)d_in[1];
    const float* Wq    = (const float*)d_in[2];
    const float* bq    = (const float*)d_in[3];
    const float* Wk    = (const float*)d_in[4];
    const float* bk    = (const float*)d_in[5];
    const float* Wv    = (const float*)d_in[6];
    const float* bv    = (const float*)d_in[7];
    const float* Wo    = (const float*)d_in[8];
    const float* bo    = (const float*)d_in[9];
    const float* gamma = (const float*)d_in[10];
    const float* beta  = (const float*)d_in[11];
    float* out = (float*)d_out;

    k0a_q<<<KSEED, DD>>>(seed, Wq, bq);
    k0b_P<<<HH, DD>>>(Wk);
    k0c_c0<<<1, 32>>>(bk);
    k1_scores_mma<<<dim3(NN / 128, BB), 256>>>(X);
    k2_stats<<<BB * OO, 256>>>();
    k3_accum_mma<<<dim3(32, BB), 256>>>(X);
    k4_final<<<dim3(KSEED, BB), 256>>>(seed, Wv, bv, Wo, bo, gamma, beta, out);
}

// round 10
// speedup vs baseline: 1.3717x; 1.1086x over previous
#include <cuda_runtime.h>
#include <cuda_bf16.h>
#include <math.h>
#include <stdint.h>

#define BB 16
#define NN 8192
#define DD 512
#define HH 8
#define KSEED 4
#define OO 32            // KSEED*HH, o = i*8 + h
#define NCH 8            // n-splits in K3

// ---- scratch (no allocations allowed; __device__ globals) ----
__device__ float g_P[OO * DD];
__device__ float g_c0[OO];
__device__ float g_S[(size_t)BB * OO * NN];        // raw scores
__device__ float g_m[BB * OO];
__device__ float g_invl[BB * OO];
__device__ float g_ypart[(size_t)BB * NCH * OO * DD];

// ---- warp-level bf16 MMA (baseline PTX, no sm_103a features needed) ----
__device__ __forceinline__ void mma_bf16(float* c, const unsigned* a,
                                         unsigned b0, unsigned b1) {
    asm volatile(
        "mma.sync.aligned.m16n8k16.row.col.f32.bf16.bf16.f32 "
        "{%0,%1,%2,%3}, {%4,%5,%6,%7}, {%8,%9}, {%0,%1,%2,%3};"
        : "+f"(c[0]), "+f"(c[1]), "+f"(c[2]), "+f"(c[3])
        : "r"(a[0]), "r"(a[1]), "r"(a[2]), "r"(a[3]), "r"(b0), "r"(b1));
}

__device__ __forceinline__ void ldsm4t(unsigned& r0, unsigned& r1,
                                       unsigned& r2, unsigned& r3,
                                       const void* p) {
    uint32_t a = (uint32_t)__cvta_generic_to_shared(p);
    asm volatile(
        "ldmatrix.sync.aligned.m8n8.x4.trans.shared.b16 {%0,%1,%2,%3}, [%4];"
        : "=r"(r0), "=r"(r1), "=r"(r2), "=r"(r3) : "r"(a));
}

// split two floats into packed bf16 hi-pair and lo-pair
__device__ __forceinline__ void split2(float a, float b, unsigned& hi, unsigned& lo) {
    __nv_bfloat16 ha = __float2bfloat16_rn(a), hb = __float2bfloat16_rn(b);
    unsigned uh = (unsigned)__bfloat16_as_ushort(ha) |
                  ((unsigned)__bfloat16_as_ushort(hb) << 16);
    __nv_bfloat16 la = __float2bfloat16_rn(a - __bfloat162float(ha));
    __nv_bfloat16 lb = __float2bfloat16_rn(b - __bfloat162float(hb));
    unsigned ul = (unsigned)__bfloat16_as_ushort(la) |
                  ((unsigned)__bfloat16_as_ushort(lb) << 16);
    hi = uh; lo = ul;
}

// ---- K0 (fused): per head h, compute q-slice, then P and c0 ----
// block h (8 blocks, 512 threads): qsh[i*64+d] = seed[i]·Wq[h*64+d] + bq;
// P[(i*8+h),c] = (1/8) sum_d qsh[i*64+d] * Wk[h*64+d, c]; c0 likewise.
__global__ void k0_fused(const float* __restrict__ seed,
                         const float* __restrict__ Wq,
                         const float* __restrict__ bq,
                         const float* __restrict__ Wk,
                         const float* __restrict__ bk) {
    __shared__ float qsh[KSEED * 64];
    int h = blockIdx.x;
    int t = threadIdx.x;
    if (t < KSEED * 64) {
        int i = t >> 6, d = t & 63;
        int g = h * 64 + d;
        const float4* w  = (const float4*)(Wq + (size_t)g * DD);
        const float4* sd = (const float4*)(seed + (size_t)i * DD);
        float acc = 0.f;
#pragma unroll 4
        for (int e4 = 0; e4 < DD / 4; e4++) {
            float4 a = w[e4], s4 = sd[e4];
            acc += a.x * s4.x + a.y * s4.y + a.z * s4.z + a.w * s4.w;
        }
        qsh[t] = acc + bq[g];
    }
    __syncthreads();
    int c = t;   // 0..511
    float acc[KSEED] = {0.f, 0.f, 0.f, 0.f};
    for (int d = 0; d < 64; d++) {
        float w = Wk[(size_t)(h * 64 + d) * DD + c];
#pragma unroll
        for (int i = 0; i < KSEED; i++) acc[i] += qsh[i * 64 + d] * w;
    }
#pragma unroll
    for (int i = 0; i < KSEED; i++)
        g_P[(size_t)(i * HH + h) * DD + c] = acc[i] * 0.125f;
    if (c < KSEED) {
        float a = 0.f;
        for (int d = 0; d < 64; d++) a += qsh[c * 64 + d] * bk[h * 64 + d];
        g_c0[c * HH + h] = a * 0.125f;
    }
}

// ============ K1: scores[b, :, nbase..nbase+128) = X_tile @ P^T + c0 ============
#define XP 72   // padded row (bf16 elements) for X tile
__global__ __launch_bounds__(256) void k1_scores_mma(const float* __restrict__ X) {
    __shared__ __align__(16) __nv_bfloat16 Xhi[128 * XP];
    __shared__ __align__(16) __nv_bfloat16 Xlo[128 * XP];
    __shared__ __align__(16) __nv_bfloat16 Phi[OO * XP];
    __shared__ __align__(16) __nv_bfloat16 Plo[OO * XP];
    __shared__ float c0s[OO];

    int t = threadIdx.x, w = t >> 5, l = t & 31;
    int b = blockIdx.y;
    int nbase = blockIdx.x * 128;
    if (t < OO) c0s[t] = g_c0[t];

    float acc[4][4];
#pragma unroll
    for (int ot = 0; ot < 4; ot++)
#pragma unroll
        for (int j = 0; j < 4; j++) acc[ot][j] = 0.f;

    const float* Xb = X + ((size_t)b * NN + nbase) * DD;

#pragma unroll 1
    for (int kc = 0; kc < 8; kc++) {
        int cbase = kc * 64;
        float4 xv[8], pv[2];
#pragma unroll
        for (int i = 0; i < 8; i++) {
            int idx = t + i * 256;
            int row = idx >> 4, q = idx & 15;
            xv[i] = *(const float4*)(Xb + (size_t)row * DD + cbase + q * 4);
        }
#pragma unroll
        for (int i = 0; i < 2; i++) {
            int idx = t + i * 256;
            int row = idx >> 4, q = idx & 15;
            pv[i] = *(const float4*)(g_P + (size_t)row * DD + cbase + q * 4);
        }
        __syncthreads();
#pragma unroll
        for (int i = 0; i < 8; i++) {
            int idx = t + i * 256;
            int row = idx >> 4, q = idx & 15;
            unsigned h0, l0, h1, l1;
            split2(xv[i].x, xv[i].y, h0, l0);
            split2(xv[i].z, xv[i].w, h1, l1);
            *(uint2*)(Xhi + row * XP + q * 4) = make_uint2(h0, h1);
            *(uint2*)(Xlo + row * XP + q * 4) = make_uint2(l0, l1);
        }
#pragma unroll
        for (int i = 0; i < 2; i++) {
            int idx = t + i * 256;
            int row = idx >> 4, q = idx & 15;
            unsigned h0, l0, h1, l1;
            split2(pv[i].x, pv[i].y, h0, l0);
            split2(pv[i].z, pv[i].w, h1, l1);
            *(uint2*)(Phi + row * XP + q * 4) = make_uint2(h0, h1);
            *(uint2*)(Plo + row * XP + q * 4) = make_uint2(l0, l1);
        }
        __syncthreads();

#pragma unroll
        for (int ks = 0; ks < 4; ks++) {
            int ar = (w * 16 + (l >> 2)) * XP + ks * 16 + (l & 3) * 2;
            unsigned ah[4], al[4];
            ah[0] = *(const unsigned*)(Xhi + ar);
            ah[1] = *(const unsigned*)(Xhi + ar + 8 * XP);
            ah[2] = *(const unsigned*)(Xhi + ar + 8);
            ah[3] = *(const unsigned*)(Xhi + ar + 8 * XP + 8);
            al[0] = *(const unsigned*)(Xlo + ar);
            al[1] = *(const unsigned*)(Xlo + ar + 8 * XP);
            al[2] = *(const unsigned*)(Xlo + ar + 8);
            al[3] = *(const unsigned*)(Xlo + ar + 8 * XP + 8);
#pragma unroll
            for (int ot = 0; ot < 4; ot++) {
                int br = (ot * 8 + (l >> 2)) * XP + ks * 16 + (l & 3) * 2;
                unsigned bh0 = *(const unsigned*)(Phi + br);
                unsigned bh1 = *(const unsigned*)(Phi + br + 8);
                unsigned bl0 = *(const unsigned*)(Plo + br);
                unsigned bl1 = *(const unsigned*)(Plo + br + 8);
                mma_bf16(acc[ot], ah, bh0, bh1);
                mma_bf16(acc[ot], ah, bl0, bl1);
                mma_bf16(acc[ot], al, bh0, bh1);
            }
        }
    }

    int row = w * 16 + (l >> 2);
    int n = nbase + row;
#pragma unroll
    for (int ot = 0; ot < 4; ot++) {
        int col = ot * 8 + 2 * (l & 3);
        g_S[((size_t)b * OO + col)     * NN + n]     = acc[ot][0] + c0s[col];
        g_S[((size_t)b * OO + col + 1) * NN + n]     = acc[ot][1] + c0s[col + 1];
        g_S[((size_t)b * OO + col)     * NN + n + 8] = acc[ot][2] + c0s[col];
        g_S[((size_t)b * OO + col + 1) * NN + n + 8] = acc[ot][3] + c0s[col + 1];
    }
}

// ---- K2: stats per (b,o): m = max, invl = 1/sum exp(s-m) ----
__global__ __launch_bounds__(256) void k2_stats() {
    int bo = blockIdx.x;
    const float4* s4 = (const float4*)(g_S + (size_t)bo * NN);
    int t = threadIdx.x;
    __shared__ float red[256];
    float m = -1e30f;
    for (int q = t; q < NN / 4; q += 256) {
        float4 v = s4[q];
        m = fmaxf(m, fmaxf(fmaxf(v.x, v.y), fmaxf(v.z, v.w)));
    }
    red[t] = m; __syncthreads();
    for (int st = 128; st > 0; st >>= 1) {
        if (t < st) red[t] = fmaxf(red[t], red[t + st]);
        __syncthreads();
    }
    m = red[0]; __syncthreads();
    float sum = 0.f;
    for (int q = t; q < NN / 4; q += 256) {
        float4 v = s4[q];
        sum += __expf(v.x - m) + __expf(v.y - m) + __expf(v.z - m) + __expf(v.w - m);
    }
    red[t] = sum; __syncthreads();
    for (int st = 128; st > 0; st >>= 1) {
        if (t < st) red[t] += red[t + st];
        __syncthreads();
    }
    if (t == 0) { g_m[bo] = m; g_invl[bo] = 1.0f / red[0]; }
}

// ============ K3: Y[b,ns][o][c] = sum_{n in ns} w[b,o,n] * X[b,n,c] ============
// grid.x = 32: ns = bx>>2 (1024-n eighth), cq = bx&3 (128-c quarter).
// Stage loads hoisted ABOVE the barrier into registers (K1 pattern) so
// LDG latency overlaps barrier wait + neighbor-CTA compute.
#define CPAD3 136   // 272 B row: 16B-aligned, conflict-free ldsm (68 words % 32 = 4)
#define WPAD 72
__global__ __launch_bounds__(256) void k3_accum_mma(const float* __restrict__ X) {
    __shared__ __align__(16) __nv_bfloat16 Xhi3[64 * CPAD3];
    __shared__ __align__(16) __nv_bfloat16 Xlo3[64 * CPAD3];
    __shared__ __align__(16) __nv_bfloat16 Whi[OO * WPAD];
    __shared__ __align__(16) __nv_bfloat16 Wlo[OO * WPAD];
    __shared__ float ms[OO], ivs[OO];

    int t = threadIdx.x, w = t >> 5, l = t & 31;
    int b = blockIdx.y;
    int ns = blockIdx.x >> 2;
    int cq = blockIdx.x & 3;
    int mh = w >> 2, wc = w & 3;

    if (t < OO) { ms[t] = g_m[b * OO + t]; ivs[t] = g_invl[b * OO + t]; }
    __syncthreads();   // ms/ivs visible before first stage transform

    float acc[4][4];
#pragma unroll
    for (int ct = 0; ct < 4; ct++)
#pragma unroll
        for (int j = 0; j < 4; j++) acc[ct][j] = 0.f;

    const float* Xb = X + (size_t)b * NN * DD + cq * 128;
    const float* Sb = g_S + (size_t)b * OO * NN;

    int lm_row = ((l >> 3) & 1) * 8 + (l & 7);
    int lm_col = (l >> 4) * 8;

#pragma unroll 1
    for (int s = 0; s < 16; s++) {
        int n0 = ns * 1024 + s * 64;
        // ---- issue stage loads BEFORE the barrier (latency hiding) ----
        float4 xv[8], sv[2];
#pragma unroll
        for (int i = 0; i < 8; i++) {
            int idx = t + i * 256;           // 0..2047
            int n = idx >> 5, qc = idx & 31;
            xv[i] = *(const float4*)(Xb + (size_t)(n0 + n) * DD + qc * 4);
        }
#pragma unroll
        for (int i = 0; i < 2; i++) {
            int idx = t + i * 256;           // 0..511
            int o = idx >> 4, q = idx & 15;
            sv[i] = *(const float4*)(Sb + (size_t)o * NN + n0 + q * 4);
        }
        __syncthreads();                     // prev stage compute done
        // ---- convert + STS ----
#pragma unroll
        for (int i = 0; i < 8; i++) {
            int idx = t + i * 256;
            int n = idx >> 5, qc = idx & 31;
            unsigned h0, l0, h1, l1;
            split2(xv[i].x, xv[i].y, h0, l0);
            split2(xv[i].z, xv[i].w, h1, l1);
            *(uint2*)(Xhi3 + n * CPAD3 + qc * 4) = make_uint2(h0, h1);
            *(uint2*)(Xlo3 + n * CPAD3 + qc * 4) = make_uint2(l0, l1);
        }
#pragma unroll
        for (int i = 0; i < 2; i++) {
            int idx = t + i * 256;
            int o = idx >> 4, q = idx & 15;
            float w0 = __expf(sv[i].x - ms[o]) * ivs[o];
            float w1 = __expf(sv[i].y - ms[o]) * ivs[o];
            float w2 = __expf(sv[i].z - ms[o]) * ivs[o];
            float w3 = __expf(sv[i].w - ms[o]) * ivs[o];
            unsigned h0, l0, h1, l1;
            split2(w0, w1, h0, l0);
            split2(w2, w3, h1, l1);
            *(uint2*)(Whi + o * WPAD + q * 4) = make_uint2(h0, h1);
            *(uint2*)(Wlo + o * WPAD + q * 4) = make_uint2(l0, l1);
        }
        __syncthreads();

        // ---- compute: 4 k16-steps x 2 c-tile-pairs x 3 combos ----
#pragma unroll
        for (int ks = 0; ks < 4; ks++) {
            int ar = (mh * 16 + (l >> 2)) * WPAD + ks * 16 + (l & 3) * 2;
            unsigned ah[4], al[4];
            ah[0] = *(const unsigned*)(Whi + ar);
            ah[1] = *(const unsigned*)(Whi + ar + 8 * WPAD);
            ah[2] = *(const unsigned*)(Whi + ar + 8);
            ah[3] = *(const unsigned*)(Whi + ar + 8 * WPAD + 8);
            al[0] = *(const unsigned*)(Wlo + ar);
            al[1] = *(const unsigned*)(Wlo + ar + 8 * WPAD);
            al[2] = *(const unsigned*)(Wlo + ar + 8);
            al[3] = *(const unsigned*)(Wlo + ar + 8 * WPAD + 8);
            int nr = (ks * 16 + lm_row) * CPAD3;
#pragma unroll
            for (int cp = 0; cp < 2; cp++) {
                int cc = wc * 32 + cp * 16 + lm_col;
                unsigned bh0, bh1, bh2, bh3, bl0, bl1, bl2, bl3;
                ldsm4t(bh0, bh1, bh2, bh3, Xhi3 + nr + cc);
                ldsm4t(bl0, bl1, bl2, bl3, Xlo3 + nr + cc);
                mma_bf16(acc[2 * cp],     ah, bh0, bh1);
                mma_bf16(acc[2 * cp],     ah, bl0, bl1);
                mma_bf16(acc[2 * cp],     al, bh0, bh1);
                mma_bf16(acc[2 * cp + 1], ah, bh2, bh3);
                mma_bf16(acc[2 * cp + 1], ah, bl2, bl3);
                mma_bf16(acc[2 * cp + 1], al, bh2, bh3);
            }
        }
    }

    // epilogue: C[row=o][col=c] -> g_ypart[b][ns][o][cq*128 + col]
    int orow = mh * 16 + (l >> 2);
    float* yp = g_ypart + ((size_t)(b * NCH + ns) * OO) * DD + cq * 128;
#pragma unroll
    for (int ct = 0; ct < 4; ct++) {
        int col = wc * 32 + (ct >> 1) * 16 + (ct & 1) * 8 + 2 * (l & 3);
        yp[(size_t)orow * DD + col]           = acc[ct][0];
        yp[(size_t)orow * DD + col + 1]       = acc[ct][1];
        yp[(size_t)(orow + 8) * DD + col]     = acc[ct][2];
        yp[(size_t)(orow + 8) * DD + col + 1] = acc[ct][3];
    }
}

// ---- K4: reduce partials, apply Wv per head, Wo, residual, LayerNorm ----
__global__ __launch_bounds__(256) void k4_final(const float* __restrict__ seed,
                                                const float* __restrict__ Wv,
                                                const float* __restrict__ bv,
                                                const float* __restrict__ Wo,
                                                const float* __restrict__ bo,
                                                const float* __restrict__ gamma,
                                                const float* __restrict__ beta,
                                                float* __restrict__ out) {
    int i = blockIdx.x;
    int b = blockIdx.y;
    int t = threadIdx.x;
    __shared__ float ysh[HH * DD];
    __shared__ float presh[DD];
    __shared__ float red[256];

    for (int idx = t; idx < HH * DD; idx += 256) {
        int h = idx >> 9, c = idx & 511;
        int o = i * HH + h;
        float s = 0.f;
#pragma unroll
        for (int ch = 0; ch < NCH; ch++)
            s += g_ypart[((size_t)(b * NCH + ch) * OO + o) * DD + c];
        ysh[idx] = s;
    }
    __syncthreads();

    for (int g = t; g < DD; g += 256) {
        int h = g >> 6;
        const float4* wr = (const float4*)(Wv + (size_t)g * DD);
        const float4* yr = (const float4*)(ysh + h * DD);
        float acc = 0.f;
#pragma unroll 4
        for (int c4 = 0; c4 < DD / 4; c4++) {
            float4 w4 = wr[c4], y4 = yr[c4];
            acc += w4.x * y4.x + w4.y * y4.y + w4.z * y4.z + w4.w * y4.w;
        }
        presh[g] = acc + bv[g];
    }
    __syncthreads();

    float zv[2];
#pragma unroll
    for (int gi = 0; gi < 2; gi++) {
        int g = t + gi * 256;
        const float4* wr = (const float4*)(Wo + (size_t)g * DD);
        const float4* pr = (const float4*)presh;
        float acc = 0.f;
#pragma unroll 4
        for (int c4 = 0; c4 < DD / 4; c4++) {
            float4 w4 = wr[c4], p4 = pr[c4];
            acc += w4.x * p4.x + w4.y * p4.y + w4.z * p4.z + w4.w * p4.w;
        }
        zv[gi] = acc + bo[g] + seed[(size_t)i * DD + g];
    }

    red[t] = zv[0] + zv[1]; __syncthreads();
    for (int st = 128; st > 0; st >>= 1) { if (t < st) red[t] += red[t + st]; __syncthreads(); }
    float mu = red[0] * (1.0f / DD); __syncthreads();
    float d0 = zv[0] - mu, d1 = zv[1] - mu;
    red[t] = d0 * d0 + d1 * d1; __syncthreads();
    for (int st = 128; st > 0; st >>= 1) { if (t < st) red[t] += red[t + st]; __syncthreads(); }
    float rstd = rsqrtf(red[0] * (1.0f / DD) + 1e-6f);

    float* op = out + ((size_t)b * KSEED + i) * DD;
#pragma unroll
    for (int gi = 0; gi < 2; gi++) {
        int g = t + gi * 256;
        op[g] = (zv[gi] - mu) * rstd * gamma[g] + beta[g];
    }
}

extern "C" void kernel_launch(void* const* d_in, const int* in_sizes, int n_in,
                              void* d_out, int out_size) {
    const float* X     = (const float*)d_in[0];
    const float* seed  = (const float*)d_in[1];
    const float* Wq    = (const float*)d_in[2];
    const float* bq    = (const float*)d_in[3];
    const float* Wk    = (const float*)d_in[4];
    const float* bk    = (const float*)d_in[5];
    const float* Wv    = (const float*)d_in[6];
    const float* bv    = (const float*)d_in[7];
    const float* Wo    = (const float*)d_in[8];
    const float* bo    = (const float*)d_in[9];
    const float* gamma = (const float*)d_in[10];
    const float* beta  = (const float*)d_in[11];
    float* out = (float*)d_out;

    k0_fused<<<HH, 512>>>(seed, Wq, bq, Wk, bk);
    k1_scores_mma<<<dim3(NN / 128, BB), 256>>>(X);
    k2_stats<<<BB * OO, 256>>>();
    k3_accum_mma<<<dim3(32, BB), 256>>>(X);
    k4_final<<<dim3(KSEED, BB), 256>>>(seed, Wv, bv, Wo, bo, gamma, beta, out);
}

// round 11
// speedup vs baseline: 1.4360x; 1.0468x over previous
#include <cuda_runtime.h>
#include <cuda_bf16.h>
#include <math.h>
#include <stdint.h>

#define BB 16
#define NN 8192
#define DD 512
#define HH 8
#define KSEED 4
#define OO 32            // KSEED*HH, o = i*8 + h
#define NCH 8            // n-splits in K3

// ---- scratch (no allocations allowed; __device__ globals) ----
__device__ float g_P[OO * DD];
__device__ float g_c0[OO];
__device__ float g_S[(size_t)BB * OO * NN];        // raw scores
__device__ float g_m[BB * OO];
__device__ float g_invl[BB * OO];
__device__ float g_ypart[(size_t)BB * NCH * OO * DD];

// ---- warp-level bf16 MMA (baseline PTX, no sm_103a features needed) ----
__device__ __forceinline__ void mma_bf16(float* c, const unsigned* a,
                                         unsigned b0, unsigned b1) {
    asm volatile(
        "mma.sync.aligned.m16n8k16.row.col.f32.bf16.bf16.f32 "
        "{%0,%1,%2,%3}, {%4,%5,%6,%7}, {%8,%9}, {%0,%1,%2,%3};"
        : "+f"(c[0]), "+f"(c[1]), "+f"(c[2]), "+f"(c[3])
        : "r"(a[0]), "r"(a[1]), "r"(a[2]), "r"(a[3]), "r"(b0), "r"(b1));
}

__device__ __forceinline__ void ldsm4t(unsigned& r0, unsigned& r1,
                                       unsigned& r2, unsigned& r3,
                                       const void* p) {
    uint32_t a = (uint32_t)__cvta_generic_to_shared(p);
    asm volatile(
        "ldmatrix.sync.aligned.m8n8.x4.trans.shared.b16 {%0,%1,%2,%3}, [%4];"
        : "=r"(r0), "=r"(r1), "=r"(r2), "=r"(r3) : "r"(a));
}

// split two floats into packed bf16 hi-pair and lo-pair
__device__ __forceinline__ void split2(float a, float b, unsigned& hi, unsigned& lo) {
    __nv_bfloat16 ha = __float2bfloat16_rn(a), hb = __float2bfloat16_rn(b);
    unsigned uh = (unsigned)__bfloat16_as_ushort(ha) |
                  ((unsigned)__bfloat16_as_ushort(hb) << 16);
    __nv_bfloat16 la = __float2bfloat16_rn(a - __bfloat162float(ha));
    __nv_bfloat16 lb = __float2bfloat16_rn(b - __bfloat162float(hb));
    unsigned ul = (unsigned)__bfloat16_as_ushort(la) |
                  ((unsigned)__bfloat16_as_ushort(lb) << 16);
    hi = uh; lo = ul;
}

// ---- K0 (fused): per head h, compute q-slice, then P and c0 ----
__global__ void k0_fused(const float* __restrict__ seed,
                         const float* __restrict__ Wq,
                         const float* __restrict__ bq,
                         const float* __restrict__ Wk,
                         const float* __restrict__ bk) {
    __shared__ float qsh[KSEED * 64];
    int h = blockIdx.x;
    int t = threadIdx.x;
    if (t < KSEED * 64) {
        int i = t >> 6, d = t & 63;
        int g = h * 64 + d;
        const float4* w  = (const float4*)(Wq + (size_t)g * DD);
        const float4* sd = (const float4*)(seed + (size_t)i * DD);
        float acc = 0.f;
#pragma unroll 4
        for (int e4 = 0; e4 < DD / 4; e4++) {
            float4 a = w[e4], s4 = sd[e4];
            acc += a.x * s4.x + a.y * s4.y + a.z * s4.z + a.w * s4.w;
        }
        qsh[t] = acc + bq[g];
    }
    __syncthreads();
    int c = t;   // 0..511
    float acc[KSEED] = {0.f, 0.f, 0.f, 0.f};
    for (int d = 0; d < 64; d++) {
        float w = Wk[(size_t)(h * 64 + d) * DD + c];
#pragma unroll
        for (int i = 0; i < KSEED; i++) acc[i] += qsh[i * 64 + d] * w;
    }
#pragma unroll
    for (int i = 0; i < KSEED; i++)
        g_P[(size_t)(i * HH + h) * DD + c] = acc[i] * 0.125f;
    if (c < KSEED) {
        float a = 0.f;
        for (int d = 0; d < 64; d++) a += qsh[c * 64 + d] * bk[h * 64 + d];
        g_c0[c * HH + h] = a * 0.125f;
    }
}

// ============ K1: scores[b, :, nbase..nbase+128) = X_tile @ P^T + c0 ============
// Software-pipelined: STS staged regs -> issue next-stage LDGs -> compute.
#define XP 72   // padded row (bf16 elements) for X tile
__global__ __launch_bounds__(256) void k1_scores_mma(const float* __restrict__ X) {
    __shared__ __align__(16) __nv_bfloat16 Xhi[128 * XP];
    __shared__ __align__(16) __nv_bfloat16 Xlo[128 * XP];
    __shared__ __align__(16) __nv_bfloat16 Phi[OO * XP];
    __shared__ __align__(16) __nv_bfloat16 Plo[OO * XP];
    __shared__ float c0s[OO];

    int t = threadIdx.x, w = t >> 5, l = t & 31;
    int b = blockIdx.y;
    int nbase = blockIdx.x * 128;
    if (t < OO) c0s[t] = g_c0[t];

    float acc[4][4];
#pragma unroll
    for (int ot = 0; ot < 4; ot++)
#pragma unroll
        for (int j = 0; j < 4; j++) acc[ot][j] = 0.f;

    const float* Xb = X + ((size_t)b * NN + nbase) * DD;

    float4 xv[8], pv[2];
    auto load_stage = [&](int kc) {
        int cbase = kc * 64;
#pragma unroll
        for (int i = 0; i < 8; i++) {
            int idx = t + i * 256;
            int row = idx >> 4, q = idx & 15;
            xv[i] = *(const float4*)(Xb + (size_t)row * DD + cbase + q * 4);
        }
#pragma unroll
        for (int i = 0; i < 2; i++) {
            int idx = t + i * 256;
            int row = idx >> 4, q = idx & 15;
            pv[i] = *(const float4*)(g_P + (size_t)row * DD + cbase + q * 4);
        }
    };

    load_stage(0);

#pragma unroll 1
    for (int kc = 0; kc < 8; kc++) {
        __syncthreads();                 // prev compute done, smem free
        // ---- STS staged regs ----
#pragma unroll
        for (int i = 0; i < 8; i++) {
            int idx = t + i * 256;
            int row = idx >> 4, q = idx & 15;
            unsigned h0, l0, h1, l1;
            split2(xv[i].x, xv[i].y, h0, l0);
            split2(xv[i].z, xv[i].w, h1, l1);
            *(uint2*)(Xhi + row * XP + q * 4) = make_uint2(h0, h1);
            *(uint2*)(Xlo + row * XP + q * 4) = make_uint2(l0, l1);
        }
#pragma unroll
        for (int i = 0; i < 2; i++) {
            int idx = t + i * 256;
            int row = idx >> 4, q = idx & 15;
            unsigned h0, l0, h1, l1;
            split2(pv[i].x, pv[i].y, h0, l0);
            split2(pv[i].z, pv[i].w, h1, l1);
            *(uint2*)(Phi + row * XP + q * 4) = make_uint2(h0, h1);
            *(uint2*)(Plo + row * XP + q * 4) = make_uint2(l0, l1);
        }
        __syncthreads();

        // ---- issue next-stage LDGs (hidden by compute below) ----
        if (kc + 1 < 8) load_stage(kc + 1);

        // ---- compute ----
#pragma unroll
        for (int ks = 0; ks < 4; ks++) {
            int ar = (w * 16 + (l >> 2)) * XP + ks * 16 + (l & 3) * 2;
            unsigned ah[4], al[4];
            ah[0] = *(const unsigned*)(Xhi + ar);
            ah[1] = *(const unsigned*)(Xhi + ar + 8 * XP);
            ah[2] = *(const unsigned*)(Xhi + ar + 8);
            ah[3] = *(const unsigned*)(Xhi + ar + 8 * XP + 8);
            al[0] = *(const unsigned*)(Xlo + ar);
            al[1] = *(const unsigned*)(Xlo + ar + 8 * XP);
            al[2] = *(const unsigned*)(Xlo + ar + 8);
            al[3] = *(const unsigned*)(Xlo + ar + 8 * XP + 8);
#pragma unroll
            for (int ot = 0; ot < 4; ot++) {
                int br = (ot * 8 + (l >> 2)) * XP + ks * 16 + (l & 3) * 2;
                unsigned bh0 = *(const unsigned*)(Phi + br);
                unsigned bh1 = *(const unsigned*)(Phi + br + 8);
                unsigned bl0 = *(const unsigned*)(Plo + br);
                unsigned bl1 = *(const unsigned*)(Plo + br + 8);
                mma_bf16(acc[ot], ah, bh0, bh1);
                mma_bf16(acc[ot], ah, bl0, bl1);
                mma_bf16(acc[ot], al, bh0, bh1);
            }
        }
    }

    int row = w * 16 + (l >> 2);
    int n = nbase + row;
#pragma unroll
    for (int ot = 0; ot < 4; ot++) {
        int col = ot * 8 + 2 * (l & 3);
        g_S[((size_t)b * OO + col)     * NN + n]     = acc[ot][0] + c0s[col];
        g_S[((size_t)b * OO + col + 1) * NN + n]     = acc[ot][1] + c0s[col + 1];
        g_S[((size_t)b * OO + col)     * NN + n + 8] = acc[ot][2] + c0s[col];
        g_S[((size_t)b * OO + col + 1) * NN + n + 8] = acc[ot][3] + c0s[col + 1];
    }
}

// ---- K2: stats per (b,o): m = max, invl = 1/sum exp(s-m) ----
__global__ __launch_bounds__(256) void k2_stats() {
    int bo = blockIdx.x;
    const float4* s4 = (const float4*)(g_S + (size_t)bo * NN);
    int t = threadIdx.x;
    __shared__ float red[256];
    float m = -1e30f;
    for (int q = t; q < NN / 4; q += 256) {
        float4 v = s4[q];
        m = fmaxf(m, fmaxf(fmaxf(v.x, v.y), fmaxf(v.z, v.w)));
    }
    red[t] = m; __syncthreads();
    for (int st = 128; st > 0; st >>= 1) {
        if (t < st) red[t] = fmaxf(red[t], red[t + st]);
        __syncthreads();
    }
    m = red[0]; __syncthreads();
    float sum = 0.f;
    for (int q = t; q < NN / 4; q += 256) {
        float4 v = s4[q];
        sum += __expf(v.x - m) + __expf(v.y - m) + __expf(v.z - m) + __expf(v.w - m);
    }
    red[t] = sum; __syncthreads();
    for (int st = 128; st > 0; st >>= 1) {
        if (t < st) red[t] += red[t + st];
        __syncthreads();
    }
    if (t == 0) { g_m[bo] = m; g_invl[bo] = 1.0f / red[0]; }
}

// ============ K3: Y[b,ns][o][c] = sum_{n in ns} w[b,o,n] * X[b,n,c] ============
// Software-pipelined like K1.
#define CPAD3 136   // 272 B row: 16B-aligned, conflict-free ldsm
#define WPAD 72
__global__ __launch_bounds__(256) void k3_accum_mma(const float* __restrict__ X) {
    __shared__ __align__(16) __nv_bfloat16 Xhi3[64 * CPAD3];
    __shared__ __align__(16) __nv_bfloat16 Xlo3[64 * CPAD3];
    __shared__ __align__(16) __nv_bfloat16 Whi[OO * WPAD];
    __shared__ __align__(16) __nv_bfloat16 Wlo[OO * WPAD];
    __shared__ float ms[OO], ivs[OO];

    int t = threadIdx.x, w = t >> 5, l = t & 31;
    int b = blockIdx.y;
    int ns = blockIdx.x >> 2;
    int cq = blockIdx.x & 3;
    int mh = w >> 2, wc = w & 3;

    if (t < OO) { ms[t] = g_m[b * OO + t]; ivs[t] = g_invl[b * OO + t]; }
    __syncthreads();

    float acc[4][4];
#pragma unroll
    for (int ct = 0; ct < 4; ct++)
#pragma unroll
        for (int j = 0; j < 4; j++) acc[ct][j] = 0.f;

    const float* Xb = X + (size_t)b * NN * DD + cq * 128;
    const float* Sb = g_S + (size_t)b * OO * NN;

    int lm_row = ((l >> 3) & 1) * 8 + (l & 7);
    int lm_col = (l >> 4) * 8;

    float4 xv[8], sv[2];
    auto load_stage = [&](int s) {
        int n0 = ns * 1024 + s * 64;
#pragma unroll
        for (int i = 0; i < 8; i++) {
            int idx = t + i * 256;
            int n = idx >> 5, qc = idx & 31;
            xv[i] = *(const float4*)(Xb + (size_t)(n0 + n) * DD + qc * 4);
        }
#pragma unroll
        for (int i = 0; i < 2; i++) {
            int idx = t + i * 256;
            int o = idx >> 4, q = idx & 15;
            sv[i] = *(const float4*)(Sb + (size_t)o * NN + n0 + q * 4);
        }
    };

    load_stage(0);

#pragma unroll 1
    for (int s = 0; s < 16; s++) {
        __syncthreads();                 // prev compute done
        // ---- STS staged regs (convert) ----
#pragma unroll
        for (int i = 0; i < 8; i++) {
            int idx = t + i * 256;
            int n = idx >> 5, qc = idx & 31;
            unsigned h0, l0, h1, l1;
            split2(xv[i].x, xv[i].y, h0, l0);
            split2(xv[i].z, xv[i].w, h1, l1);
            *(uint2*)(Xhi3 + n * CPAD3 + qc * 4) = make_uint2(h0, h1);
            *(uint2*)(Xlo3 + n * CPAD3 + qc * 4) = make_uint2(l0, l1);
        }
#pragma unroll
        for (int i = 0; i < 2; i++) {
            int idx = t + i * 256;
            int o = idx >> 4, q = idx & 15;
            float w0 = __expf(sv[i].x - ms[o]) * ivs[o];
            float w1 = __expf(sv[i].y - ms[o]) * ivs[o];
            float w2 = __expf(sv[i].z - ms[o]) * ivs[o];
            float w3 = __expf(sv[i].w - ms[o]) * ivs[o];
            unsigned h0, l0, h1, l1;
            split2(w0, w1, h0, l0);
            split2(w2, w3, h1, l1);
            *(uint2*)(Whi + o * WPAD + q * 4) = make_uint2(h0, h1);
            *(uint2*)(Wlo + o * WPAD + q * 4) = make_uint2(l0, l1);
        }
        __syncthreads();

        // ---- issue next-stage LDGs (hidden by compute below) ----
        if (s + 1 < 16) load_stage(s + 1);

        // ---- compute: 4 k16-steps x 2 c-tile-pairs x 3 combos ----
#pragma unroll
        for (int ks = 0; ks < 4; ks++) {
            int ar = (mh * 16 + (l >> 2)) * WPAD + ks * 16 + (l & 3) * 2;
            unsigned ah[4], al[4];
            ah[0] = *(const unsigned*)(Whi + ar);
            ah[1] = *(const unsigned*)(Whi + ar + 8 * WPAD);
            ah[2] = *(const unsigned*)(Whi + ar + 8);
            ah[3] = *(const unsigned*)(Whi + ar + 8 * WPAD + 8);
            al[0] = *(const unsigned*)(Wlo + ar);
            al[1] = *(const unsigned*)(Wlo + ar + 8 * WPAD);
            al[2] = *(const unsigned*)(Wlo + ar + 8);
            al[3] = *(const unsigned*)(Wlo + ar + 8 * WPAD + 8);
            int nr = (ks * 16 + lm_row) * CPAD3;
#pragma unroll
            for (int cp = 0; cp < 2; cp++) {
                int cc = wc * 32 + cp * 16 + lm_col;
                unsigned bh0, bh1, bh2, bh3, bl0, bl1, bl2, bl3;
                ldsm4t(bh0, bh1, bh2, bh3, Xhi3 + nr + cc);
                ldsm4t(bl0, bl1, bl2, bl3, Xlo3 + nr + cc);
                mma_bf16(acc[2 * cp],     ah, bh0, bh1);
                mma_bf16(acc[2 * cp],     ah, bl0, bl1);
                mma_bf16(acc[2 * cp],     al, bh0, bh1);
                mma_bf16(acc[2 * cp + 1], ah, bh2, bh3);
                mma_bf16(acc[2 * cp + 1], ah, bl2, bl3);
                mma_bf16(acc[2 * cp + 1], al, bh2, bh3);
            }
        }
    }

    int orow = mh * 16 + (l >> 2);
    float* yp = g_ypart + ((size_t)(b * NCH + ns) * OO) * DD + cq * 128;
#pragma unroll
    for (int ct = 0; ct < 4; ct++) {
        int col = wc * 32 + (ct >> 1) * 16 + (ct & 1) * 8 + 2 * (l & 3);
        yp[(size_t)orow * DD + col]           = acc[ct][0];
        yp[(size_t)orow * DD + col + 1]       = acc[ct][1];
        yp[(size_t)(orow + 8) * DD + col]     = acc[ct][2];
        yp[(size_t)(orow + 8) * DD + col + 1] = acc[ct][3];
    }
}

// ---- K4: reduce partials, apply Wv per head, Wo, residual, LayerNorm ----
__global__ __launch_bounds__(256) void k4_final(const float* __restrict__ seed,
                                                const float* __restrict__ Wv,
                                                const float* __restrict__ bv,
                                                const float* __restrict__ Wo,
                                                const float* __restrict__ bo,
                                                const float* __restrict__ gamma,
                                                const float* __restrict__ beta,
                                                float* __restrict__ out) {
    int i = blockIdx.x;
    int b = blockIdx.y;
    int t = threadIdx.x;
    __shared__ float ysh[HH * DD];
    __shared__ float presh[DD];
    __shared__ float red[256];

    for (int idx = t; idx < HH * DD; idx += 256) {
        int h = idx >> 9, c = idx & 511;
        int o = i * HH + h;
        float s = 0.f;
#pragma unroll
        for (int ch = 0; ch < NCH; ch++)
            s += g_ypart[((size_t)(b * NCH + ch) * OO + o) * DD + c];
        ysh[idx] = s;
    }
    __syncthreads();

    for (int g = t; g < DD; g += 256) {
        int h = g >> 6;
        const float4* wr = (const float4*)(Wv + (size_t)g * DD);
        const float4* yr = (const float4*)(ysh + h * DD);
        float acc = 0.f;
#pragma unroll 4
        for (int c4 = 0; c4 < DD / 4; c4++) {
            float4 w4 = wr[c4], y4 = yr[c4];
            acc += w4.x * y4.x + w4.y * y4.y + w4.z * y4.z + w4.w * y4.w;
        }
        presh[g] = acc + bv[g];
    }
    __syncthreads();

    float zv[2];
#pragma unroll
    for (int gi = 0; gi < 2; gi++) {
        int g = t + gi * 256;
        const float4* wr = (const float4*)(Wo + (size_t)g * DD);
        const float4* pr = (const float4*)presh;
        float acc = 0.f;
#pragma unroll 4
        for (int c4 = 0; c4 < DD / 4; c4++) {
            float4 w4 = wr[c4], p4 = pr[c4];
            acc += w4.x * p4.x + w4.y * p4.y + w4.z * p4.z + w4.w * p4.w;
        }
        zv[gi] = acc + bo[g] + seed[(size_t)i * DD + g];
    }

    red[t] = zv[0] + zv[1]; __syncthreads();
    for (int st = 128; st > 0; st >>= 1) { if (t < st) red[t] += red[t + st]; __syncthreads(); }
    float mu = red[0] * (1.0f / DD); __syncthreads();
    float d0 = zv[0] - mu, d1 = zv[1] - mu;
    red[t] = d0 * d0 + d1 * d1; __syncthreads();
    for (int st = 128; st > 0; st >>= 1) { if (t < st) red[t] += red[t + st]; __syncthreads(); }
    float rstd = rsqrtf(red[0] * (1.0f / DD) + 1e-6f);

    float* op = out + ((size_t)b * KSEED + i) * DD;
#pragma unroll
    for (int gi = 0; gi < 2; gi++) {
        int g = t + gi * 256;
        op[g] = (zv[gi] - mu) * rstd * gamma[g] + beta[g];
    }
}

extern "C" void kernel_launch(void* const* d_in, const int* in_sizes, int n_in,
                              void* d_out, int out_size) {
    const float* X     = (const float*)d_in[0];
    const float* seed  = (const float*)d_in[1];
    const float* Wq    = (const float*)d_in[2];
    const float* bq    = (const float*)d_in[3];
    const float* Wk    = (const float*)d_in[4];
    const float* bk    = (const float*)d_in[5];
    const float* Wv    = (const float*)d_in[6];
    const float* bv    = (const float*)d_in[7];
    const float* Wo    = (const float*)d_in[8];
    const float* bo    = (const float*)d_in[9];
    const float* gamma = (const float*)d_in[10];
    const float* beta  = (const float*)d_in[11];
    float* out = (float*)d_out;

    k0_fused<<<HH, 512>>>(seed, Wq, bq, Wk, bk);
    k1_scores_mma<<<dim3(NN / 128, BB), 256>>>(X);
    k2_stats<<<BB * OO, 256>>>();
    k3_accum_mma<<<dim3(32, BB), 256>>>(X);
    k4_final<<<dim3(KSEED, BB), 256>>>(seed, Wv, bv, Wo, bo, gamma, beta, out);
}